// round 12
// baseline (speedup 1.0000x reference)
#include <cuda_runtime.h>
#include <cuda_bf16.h>
#include <cstdint>

#define NN 8192
#define DD 256
#define XSTR 259

// ---------------- device scratch ----------------
__device__ __nv_bfloat16 g_Xbf[NN * DD];
__device__ __nv_bfloat16 g_Wbf[3][DD * DD];
__device__ __nv_bfloat16 g_Qbf[NN * DD];
__device__ __nv_bfloat16 g_Kbf[NN * DD];
__device__ __nv_bfloat16 g_Vbf[NN * DD];
__device__ float4 g_P4[NN];   // scaled: (c*px, c*py, c*pz, c^2*|p|^2), c^2 = 0.5*log2(e)

// ---------------- helpers ----------------
__device__ __forceinline__ uint32_t smem_u32(const void* p) {
    uint32_t a;
    asm("{ .reg .u64 t; cvta.to.shared.u64 t, %1; cvt.u32.u64 %0, t; }" : "=r"(a) : "l"(p));
    return a;
}
__device__ __forceinline__ float fexp2(float x) {   // fast 2^x (MUFU.EX2)
    float r;
    asm("ex2.approx.f32 %0, %1;" : "=f"(r) : "f"(x));
    return r;
}
__device__ __forceinline__ uint32_t pack_bf16(float lo, float hi) {
    uint32_t r;
    asm("cvt.rn.bf16x2.f32 %0, %1, %2;" : "=r"(r) : "f"(hi), "f"(lo));
    return r;
}
__device__ __forceinline__ void cp16(uint32_t s, const void* g) {
    asm volatile("cp.async.cg.shared.global [%0], [%1], 16;" :: "r"(s), "l"(g));
}
__device__ __forceinline__ void cp_commit() {
    asm volatile("cp.async.commit_group;" ::: "memory");
}
__device__ __forceinline__ void ldm4(uint32_t* r, uint32_t a) {
    asm volatile("ldmatrix.sync.aligned.m8n8.x4.shared.b16 {%0,%1,%2,%3}, [%4];"
                 : "=r"(r[0]), "=r"(r[1]), "=r"(r[2]), "=r"(r[3]) : "r"(a));
}
__device__ __forceinline__ void ldm4t(uint32_t* r, uint32_t a) {
    asm volatile("ldmatrix.sync.aligned.m8n8.x4.trans.shared.b16 {%0,%1,%2,%3}, [%4];"
                 : "=r"(r[0]), "=r"(r[1]), "=r"(r[2]), "=r"(r[3]) : "r"(a));
}
__device__ __forceinline__ void mma16816(float* c, const uint32_t* a, uint32_t b0, uint32_t b1) {
    asm volatile(
        "mma.sync.aligned.m16n8k16.row.col.f32.bf16.bf16.f32 "
        "{%0,%1,%2,%3}, {%4,%5,%6,%7}, {%8,%9}, {%0,%1,%2,%3};"
        : "+f"(c[0]), "+f"(c[1]), "+f"(c[2]), "+f"(c[3])
        : "r"(a[0]), "r"(a[1]), "r"(a[2]), "r"(a[3]), "r"(b0), "r"(b1));
}

// ---------------------------------------------------------------------------
// K0: prep — X -> bf16, scaled positions (X rows only 4B-aligned: scalar loads)
// ---------------------------------------------------------------------------
__global__ __launch_bounds__(256) void prep_kernel(const float* __restrict__ X)
{
    int idx = blockIdx.x * 256 + threadIdx.x;
    int row = idx >> 5, c8 = idx & 31;
    const float* xr = X + (size_t)row * XSTR + c8 * 8;
    float v0 = xr[0], v1 = xr[1], v2 = xr[2], v3 = xr[3];
    float v4 = xr[4], v5 = xr[5], v6 = xr[6], v7 = xr[7];
    uint4 u;
    u.x = pack_bf16(v0, v1); u.y = pack_bf16(v2, v3);
    u.z = pack_bf16(v4, v5); u.w = pack_bf16(v6, v7);
    *(uint4*)&g_Xbf[(size_t)row * DD + c8 * 8] = u;
    if (c8 == 0) {
        const float c = 0.84932180f;          // sqrt(0.5*log2(e))
        float px = X[(size_t)row * XSTR + 256] * c;
        float py = X[(size_t)row * XSTR + 257] * c;
        float pz = X[(size_t)row * XSTR + 258] * c;
        g_P4[row] = make_float4(px, py, pz, px*px + py*py + pz*pz);
    }
}

// ---------------------------------------------------------------------------
// K0b: W -> bf16 (Q folded with 1/16)
// ---------------------------------------------------------------------------
__global__ __launch_bounds__(256) void wconv_kernel(
    const float* __restrict__ WQ, const float* __restrict__ WK, const float* __restrict__ WV)
{
    int mat = blockIdx.y;
    const float* W = (mat == 0) ? WQ : (mat == 1) ? WK : WV;
    float sc = (mat == 0) ? 0.0625f : 1.0f;
    int idx = blockIdx.x * 256 + threadIdx.x;
    int base = idx * 8;
    const float4* wr = (const float4*)(W + base);
    float4 a = wr[0], b = wr[1];
    uint4 u;
    u.x = pack_bf16(a.x*sc, a.y*sc); u.y = pack_bf16(a.z*sc, a.w*sc);
    u.z = pack_bf16(b.x*sc, b.y*sc); u.w = pack_bf16(b.z*sc, b.w*sc);
    *(uint4*)&g_Wbf[mat][base] = u;
}

// ---------------------------------------------------------------------------
// K1: QKV via mma.sync.  grid (64, 3), 256 thr
// ---------------------------------------------------------------------------
#define QX 0
#define QW 67584
#define SMEMQ (67584 + 135168)

__global__ __launch_bounds__(256, 1) void qkv_mma_kernel(
    const float* __restrict__ bQ, const float* __restrict__ bK, const float* __restrict__ bV)
{
    extern __shared__ char sm[];
    const uint32_t sb = smem_u32(sm);
    const int t = threadIdx.x, lane = t & 31, w = t >> 5;
    const int g = lane >> 2, t4 = lane & 3;
    const int mat = blockIdx.y;
    const int i0 = blockIdx.x * 128;
    const float* bias = (mat == 0) ? bQ : (mat == 1) ? bK : bV;
    const float bsc = (mat == 0) ? 0.0625f : 1.0f;
    __nv_bfloat16* O = (mat == 0) ? g_Qbf : (mat == 1) ? g_Kbf : g_Vbf;

    #pragma unroll
    for (int l = 0; l < 16; l++) {
        int idx = t + l * 256;
        int r = idx >> 5, c8 = idx & 31;
        uint4 v = *(const uint4*)&g_Xbf[(size_t)(i0 + r) * DD + c8 * 8];
        *(uint4*)(sm + QX + r * 528 + c8 * 16) = v;
    }
    #pragma unroll
    for (int l = 0; l < 32; l++) {
        int idx = t + l * 256;
        int r = idx >> 5, c8 = idx & 31;
        uint4 v = *(const uint4*)&g_Wbf[mat][(size_t)r * DD + c8 * 8];
        *(uint4*)(sm + QW + r * 528 + c8 * 16) = v;
    }
    __syncthreads();

    float o[32][4];
    #pragma unroll
    for (int i = 0; i < 32; i++)
        #pragma unroll
        for (int j = 0; j < 4; j++) o[i][j] = 0.f;

    const int arow = w * 16 + (lane & 15);
    const int acol = (lane >> 4) * 8;
    const int vrow_off = ((lane >> 3) & 1) * 8 + (lane & 7);
    const int vcol_off = (lane >> 4) * 8;

    #pragma unroll
    for (int k = 0; k < 16; k++) {
        uint32_t Aa[4];
        ldm4(Aa, sb + QX + arow * 528 + (acol + k * 16) * 2);
        #pragma unroll
        for (int n16 = 0; n16 < 16; n16++) {
            uint32_t vb[4];
            ldm4t(vb, sb + QW + (k * 16 + vrow_off) * 528 + (n16 * 16 + vcol_off) * 2);
            mma16816(o[n16 * 2],     Aa, vb[0], vb[1]);
            mma16816(o[n16 * 2 + 1], Aa, vb[2], vb[3]);
        }
    }

    const int row0 = i0 + w * 16 + g;
    #pragma unroll
    for (int nb = 0; nb < 32; nb++) {
        int c = nb * 8 + t4 * 2;
        float b0 = bias[c] * bsc, b1 = bias[c + 1] * bsc;
        *(uint32_t*)&O[(size_t)row0 * DD + c]       = pack_bf16(o[nb][0] + b0, o[nb][1] + b1);
        *(uint32_t*)&O[(size_t)(row0 + 8) * DD + c] = pack_bf16(o[nb][2] + b0, o[nb][3] + b1);
    }
}

// ---------------------------------------------------------------------------
// K2: flash attention.  BM=32, grid 256, 256 thr, 2 CTAs/SM (independent —
// no cross-CTA coupling; the co-resident CTA fills issue slots during this
// CTA's barriers/loads).  32-key tiles, 256 iterations.
//   S phase : warps 0-3 as (rh, kh): rows rh*16..+16 x keys kh*16..+16
//   AV phase: all 8 warps (rh, dq): rows rh*16..+16 x dims dq*64..+64, 32 keys
// Unshifted-exp softmax-one; decay via ex2 on pre-scaled positions.
// ---------------------------------------------------------------------------
#define SQ    0                      // 32*528 = 16896
#define SK    16896                  // 2 x 16896
#define SV    50688                  // 2 x 16896
#define SP    84480                  // 32 x 80 = 2560
#define SPK   87040                  // 2 x 512
#define SRED  88064                  // m[2][32], l[2][32] = 512
#define SMEMB 88576

__device__ __forceinline__ void loadK32(uint32_t sb, int t, int tt)
{
    if (tt < 256) {
        const int j0 = tt * 32;
        #pragma unroll
        for (int l = 0; l < 4; l++) {
            int idx = t + l * 256;
            int r = idx >> 5, c8 = idx & 31;
            cp16(sb + SK + (tt & 1) * 16896 + (uint32_t)(r * 528 + c8 * 16),
                 (const char*)g_Kbf + ((size_t)(j0 + r) * DD + c8 * 8) * 2);
        }
        if (t < 32) cp16(sb + SPK + (tt & 1) * 512 + t * 16, &g_P4[j0 + t]);
    }
    cp_commit();
}
__device__ __forceinline__ void loadV32(uint32_t sb, int t, int tt)
{
    if (tt < 256) {
        const int j0 = tt * 32;
        #pragma unroll
        for (int l = 0; l < 4; l++) {
            int idx = t + l * 256;
            int r = idx >> 5, c8 = idx & 31;
            cp16(sb + SV + (tt & 1) * 16896 + (uint32_t)(r * 528 + c8 * 16),
                 (const char*)g_Vbf + ((size_t)(j0 + r) * DD + c8 * 8) * 2);
        }
    }
    cp_commit();
}

__global__ __launch_bounds__(256, 2) void flash_kernel(
    const float* __restrict__ X, float* __restrict__ out)
{
    extern __shared__ char sm[];
    const uint32_t sb = smem_u32(sm);
    const int t = threadIdx.x;
    const int lane = t & 31, w = t >> 5;
    const int rh = w & 1;                 // row half (0/1) — S and AV
    const int kh = (w >> 1) & 1;          // S: key half (warps 0-3)
    const int dq = w >> 1;                // AV: dim quarter (0..3)
    const int lg = lane >> 2, t4 = lane & 3;
    const int i0 = blockIdx.x * 32;
    const int rA = rh * 16 + lg, rB = rA + 8;

    // stage Q (32 x 256 bf16)
    #pragma unroll
    for (int l = 0; l < 4; l++) {
        int idx = t + l * 256;
        int r = idx >> 5, c8 = idx & 31;
        uint4 v = *(const uint4*)&g_Qbf[(size_t)(i0 + r) * DD + c8 * 8];
        *(uint4*)(sm + SQ + r * 528 + c8 * 16) = v;
    }
    loadK32(sb, t, 0);
    loadV32(sb, t, 0);
    loadK32(sb, t, 1);
    loadV32(sb, t, 1);

    const float4 pqA = g_P4[i0 + rA];
    const float4 pqB = g_P4[i0 + rB];
    __syncthreads();

    float o[8][4];
    #pragma unroll
    for (int i = 0; i < 8; i++)
        #pragma unroll
        for (int j = 0; j < 4; j++) o[i][j] = 0.f;
    float mA = -1e30f, mB = -1e30f;
    float lA = 0.f, lB = 0.f;

    const int qrow = rh * 16 + (lane & 15);
    const int qcol = (lane >> 4) * 8;
    const int krow = kh * 16 + ((lane >> 4) << 3) + (lane & 7);
    const int kcol_off = ((lane >> 3) & 1) * 8;
    const int prow = rh * 16 + (lane & 15);
    const int pcol = (lane >> 4) * 8;
    const int vrow_off = ((lane >> 3) & 1) * 8 + (lane & 7);
    const int vcol_off = (lane >> 4) * 8;

    #pragma unroll 1
    for (int tt = 0; tt < 256; tt++) {
        const int b = tt & 1;
        asm volatile("cp.async.wait_group 2;" ::: "memory");   // K(tt), V(tt) done
        __syncthreads();

        // ---- S (warps 0-3): 16 rows x 16 keys ----
        if (w < 4) {
            const uint32_t kbase = sb + SK + b * 16896;
            float s[2][4];
            #pragma unroll
            for (int i = 0; i < 2; i++)
                #pragma unroll
                for (int j = 0; j < 4; j++) s[i][j] = 0.f;
            #pragma unroll
            for (int k = 0; k < 16; k++) {
                uint32_t Qa[4], bf[4];
                ldm4(Qa, sb + SQ + qrow * 528 + (qcol + k * 16) * 2);
                ldm4(bf, kbase + krow * 528 + (k * 16 + kcol_off) * 2);
                mma16816(s[0], Qa, bf[0], bf[1]);
                mma16816(s[1], Qa, bf[2], bf[3]);
            }

            // decay (prescaled, ex2) + unshifted exp -> P smem
            const float4* pk = (const float4*)(sm + SPK + b * 512);
            const float L2E = 1.4426950408889634f;
            #pragma unroll
            for (int nb = 0; nb < 2; nb++) {
                int c0 = kh * 16 + nb * 8 + t4 * 2;
                float4 k0 = pk[c0], k1 = pk[c0 + 1];
                float dA0 = pqA.w + k0.w - 2.f*(pqA.x*k0.x + pqA.y*k0.y + pqA.z*k0.z);
                float dA1 = pqA.w + k1.w - 2.f*(pqA.x*k1.x + pqA.y*k1.y + pqA.z*k1.z);
                float dB0 = pqB.w + k0.w - 2.f*(pqB.x*k0.x + pqB.y*k0.y + pqB.z*k0.z);
                float dB1 = pqB.w + k1.w - 2.f*(pqB.x*k1.x + pqB.y*k1.y + pqB.z*k1.z);
                float x0 = s[nb][0] * fexp2(-fmaxf(dA0, 0.f));
                float x1 = s[nb][1] * fexp2(-fmaxf(dA1, 0.f));
                float x2 = s[nb][2] * fexp2(-fmaxf(dB0, 0.f));
                float x3 = s[nb][3] * fexp2(-fmaxf(dB1, 0.f));
                mA = fmaxf(mA, fmaxf(x0, x1));
                mB = fmaxf(mB, fmaxf(x2, x3));
                float p0 = fexp2(x0 * L2E), p1 = fexp2(x1 * L2E);
                float p2 = fexp2(x2 * L2E), p3 = fexp2(x3 * L2E);
                lA += p0 + p1; lB += p2 + p3;
                *(uint32_t*)(sm + SP + rA * 80 + c0 * 2) = pack_bf16(p0, p1);
                *(uint32_t*)(sm + SP + rB * 80 + c0 * 2) = pack_bf16(p2, p3);
            }
        }
        __syncthreads();            // P ready; K(tt)+pk(tt) dead
        loadK32(sb, t, tt + 2);     // overlap K prefetch with AV

        // ---- AV (all 8 warps): 16 rows x 64 dims, 32 keys ----
        const uint32_t vbase = sb + SV + b * 16896;
        #pragma unroll
        for (int ks = 0; ks < 2; ks++) {
            uint32_t Pa[4];
            ldm4(Pa, sb + SP + prow * 80 + (ks * 16 + pcol) * 2);
            #pragma unroll
            for (int n16 = 0; n16 < 4; n16++) {
                uint32_t vb[4];
                ldm4t(vb, vbase + (ks * 16 + vrow_off) * 528
                                + (dq * 64 + n16 * 16 + vcol_off) * 2);
                mma16816(o[n16 * 2],     Pa, vb[0], vb[1]);
                mma16816(o[n16 * 2 + 1], Pa, vb[2], vb[3]);
            }
        }
        __syncthreads();            // V(tt) + P consumed
        loadV32(sb, t, tt + 2);
    }

    // ---- reduce l/m: quad lanes, then across kh halves via smem ----
    float* red = (float*)(sm + SRED);   // m[2][32] then l[2][32]
    if (w < 4) {
        lA += __shfl_xor_sync(0xffffffffu, lA, 1);
        lA += __shfl_xor_sync(0xffffffffu, lA, 2);
        lB += __shfl_xor_sync(0xffffffffu, lB, 1);
        lB += __shfl_xor_sync(0xffffffffu, lB, 2);
        mA = fmaxf(mA, __shfl_xor_sync(0xffffffffu, mA, 1));
        mA = fmaxf(mA, __shfl_xor_sync(0xffffffffu, mA, 2));
        mB = fmaxf(mB, __shfl_xor_sync(0xffffffffu, mB, 1));
        mB = fmaxf(mB, __shfl_xor_sync(0xffffffffu, mB, 2));
        if (t4 == 0) {
            red[kh * 32 + rA] = mA;      red[kh * 32 + rB] = mB;
            red[64 + kh * 32 + rA] = lA; red[64 + kh * 32 + rB] = lB;
        }
    }
    __syncthreads();
    {
        const float L2E = 1.4426950408889634f;
        float MA = fmaxf(red[rA], red[32 + rA]);
        float MB = fmaxf(red[rB], red[32 + rB]);
        float invA = 1.f / (fexp2(MA * L2E) + red[64 + rA] + red[96 + rA]);
        float invB = 1.f / (fexp2(MB * L2E) + red[64 + rB] + red[96 + rB]);
        const int gA = i0 + rA, gB = i0 + rB;
        #pragma unroll
        for (int nb = 0; nb < 8; nb++) {
            int c = dq * 64 + nb * 8 + t4 * 2;
            float2 vA, vB;
            vA.x = o[nb][0] * invA + X[(size_t)gA * XSTR + c];
            vA.y = o[nb][1] * invA + X[(size_t)gA * XSTR + c + 1];
            vB.x = o[nb][2] * invB + X[(size_t)gB * XSTR + c];
            vB.y = o[nb][3] * invB + X[(size_t)gB * XSTR + c + 1];
            *(float2*)&out[(size_t)gA * DD + c] = vA;
            *(float2*)&out[(size_t)gB * DD + c] = vB;
        }
    }
}

// ---------------------------------------------------------------------------
extern "C" void kernel_launch(void* const* d_in, const int* in_sizes, int n_in,
                              void* d_out, int out_size)
{
    const float* X  = (const float*)d_in[0];
    const float* WQ = (const float*)d_in[1];
    const float* bQ = (const float*)d_in[2];
    const float* WK = (const float*)d_in[3];
    const float* bK = (const float*)d_in[4];
    const float* WV = (const float*)d_in[5];
    const float* bV = (const float*)d_in[6];
    float* out = (float*)d_out;

    cudaFuncSetAttribute(flash_kernel, cudaFuncAttributeMaxDynamicSharedMemorySize, SMEMB);
    cudaFuncSetAttribute(qkv_mma_kernel, cudaFuncAttributeMaxDynamicSharedMemorySize, SMEMQ);

    prep_kernel<<<NN * 32 / 256, 256>>>(X);
    wconv_kernel<<<dim3(DD * DD / 8 / 256, 3), 256>>>(WQ, WK, WV);
    qkv_mma_kernel<<<dim3(NN / 128, 3), 256, SMEMQ>>>(bQ, bK, bV);
    flash_kernel<<<NN / 32, 256, SMEMB>>>(X, out);
}

// round 13
// speedup vs baseline: 1.3915x; 1.3915x over previous
#include <cuda_runtime.h>
#include <cuda_bf16.h>
#include <cstdint>

#define NN 8192
#define DD 256
#define XSTR 259

// ---------------- device scratch ----------------
__device__ __nv_bfloat16 g_Xbf[NN * DD];
__device__ __nv_bfloat16 g_Wbf[3][DD * DD];
__device__ uint8_t g_Qf8[NN * DD];            // Q e4m3 (UNSCALED; /16 folded into decay)
__device__ uint8_t g_Kf8[NN * DD];            // K e4m3
__device__ __nv_bfloat16 g_Vbf[NN * DD];
__device__ float4 g_P4[NN];   // scaled: (c*px, c*py, c*pz, c^2*|p|^2), c^2 = 0.5*log2(e)

// ---------------- helpers ----------------
__device__ __forceinline__ uint32_t smem_u32(const void* p) {
    uint32_t a;
    asm("{ .reg .u64 t; cvta.to.shared.u64 t, %1; cvt.u32.u64 %0, t; }" : "=r"(a) : "l"(p));
    return a;
}
__device__ __forceinline__ float fexp2(float x) {
    float r;
    asm("ex2.approx.f32 %0, %1;" : "=f"(r) : "f"(x));
    return r;
}
__device__ __forceinline__ uint32_t pack_bf16(float lo, float hi) {
    uint32_t r;
    asm("cvt.rn.bf16x2.f32 %0, %1, %2;" : "=r"(r) : "f"(hi), "f"(lo));
    return r;
}
__device__ __forceinline__ uint16_t pack_e4m3x2(float lo, float hi) {
    uint16_t r;
    asm("cvt.rn.satfinite.e4m3x2.f32 %0, %1, %2;" : "=h"(r) : "f"(hi), "f"(lo));
    return r;
}
__device__ __forceinline__ void cp16(uint32_t s, const void* g) {
    asm volatile("cp.async.cg.shared.global [%0], [%1], 16;" :: "r"(s), "l"(g));
}
__device__ __forceinline__ void cp_commit() {
    asm volatile("cp.async.commit_group;" ::: "memory");
}
__device__ __forceinline__ void ldm4(uint32_t* r, uint32_t a) {
    asm volatile("ldmatrix.sync.aligned.m8n8.x4.shared.b16 {%0,%1,%2,%3}, [%4];"
                 : "=r"(r[0]), "=r"(r[1]), "=r"(r[2]), "=r"(r[3]) : "r"(a));
}
__device__ __forceinline__ void ldm4t(uint32_t* r, uint32_t a) {
    asm volatile("ldmatrix.sync.aligned.m8n8.x4.trans.shared.b16 {%0,%1,%2,%3}, [%4];"
                 : "=r"(r[0]), "=r"(r[1]), "=r"(r[2]), "=r"(r[3]) : "r"(a));
}
__device__ __forceinline__ void mma16816(float* c, const uint32_t* a, uint32_t b0, uint32_t b1) {
    asm volatile(
        "mma.sync.aligned.m16n8k16.row.col.f32.bf16.bf16.f32 "
        "{%0,%1,%2,%3}, {%4,%5,%6,%7}, {%8,%9}, {%0,%1,%2,%3};"
        : "+f"(c[0]), "+f"(c[1]), "+f"(c[2]), "+f"(c[3])
        : "r"(a[0]), "r"(a[1]), "r"(a[2]), "r"(a[3]), "r"(b0), "r"(b1));
}
__device__ __forceinline__ void mma_fp8(float* c, const uint32_t* a, uint32_t b0, uint32_t b1) {
    asm volatile(
        "mma.sync.aligned.m16n8k32.row.col.f32.e4m3.e4m3.f32 "
        "{%0,%1,%2,%3}, {%4,%5,%6,%7}, {%8,%9}, {%0,%1,%2,%3};"
        : "+f"(c[0]), "+f"(c[1]), "+f"(c[2]), "+f"(c[3])
        : "r"(a[0]), "r"(a[1]), "r"(a[2]), "r"(a[3]), "r"(b0), "r"(b1));
}
__device__ __forceinline__ void bar_sync(int id, int cnt) {
    asm volatile("bar.sync %0, %1;" :: "r"(id), "r"(cnt) : "memory");
}

// ---------------------------------------------------------------------------
// K0: prep — X -> bf16, scaled positions (X rows only 4B-aligned: scalar loads)
// ---------------------------------------------------------------------------
__global__ __launch_bounds__(256) void prep_kernel(const float* __restrict__ X)
{
    int idx = blockIdx.x * 256 + threadIdx.x;
    int row = idx >> 5, c8 = idx & 31;
    const float* xr = X + (size_t)row * XSTR + c8 * 8;
    float v0 = xr[0], v1 = xr[1], v2 = xr[2], v3 = xr[3];
    float v4 = xr[4], v5 = xr[5], v6 = xr[6], v7 = xr[7];
    uint4 u;
    u.x = pack_bf16(v0, v1); u.y = pack_bf16(v2, v3);
    u.z = pack_bf16(v4, v5); u.w = pack_bf16(v6, v7);
    *(uint4*)&g_Xbf[(size_t)row * DD + c8 * 8] = u;
    if (c8 == 0) {
        const float c = 0.84932180f;          // sqrt(0.5*log2(e))
        float px = X[(size_t)row * XSTR + 256] * c;
        float py = X[(size_t)row * XSTR + 257] * c;
        float pz = X[(size_t)row * XSTR + 258] * c;
        g_P4[row] = make_float4(px, py, pz, px*px + py*py + pz*pz);
    }
}

// ---------------------------------------------------------------------------
// K0b: W -> bf16 (no scaling; /16 folded into decay exponent)
// ---------------------------------------------------------------------------
__global__ __launch_bounds__(256) void wconv_kernel(
    const float* __restrict__ WQ, const float* __restrict__ WK, const float* __restrict__ WV)
{
    int mat = blockIdx.y;
    const float* W = (mat == 0) ? WQ : (mat == 1) ? WK : WV;
    int idx = blockIdx.x * 256 + threadIdx.x;
    int base = idx * 8;
    const float4* wr = (const float4*)(W + base);
    float4 a = wr[0], b = wr[1];
    uint4 u;
    u.x = pack_bf16(a.x, a.y); u.y = pack_bf16(a.z, a.w);
    u.z = pack_bf16(b.x, b.y); u.w = pack_bf16(b.z, b.w);
    *(uint4*)&g_Wbf[mat][base] = u;
}

// ---------------------------------------------------------------------------
// K1: QKV via mma.sync.  grid (64, 3), 256 thr.  Q/K -> e4m3, V -> bf16.
// ---------------------------------------------------------------------------
#define QX 0
#define QW 67584
#define SMEMQ (67584 + 135168)

__global__ __launch_bounds__(256, 1) void qkv_mma_kernel(
    const float* __restrict__ bQ, const float* __restrict__ bK, const float* __restrict__ bV)
{
    extern __shared__ char sm[];
    const uint32_t sb = smem_u32(sm);
    const int t = threadIdx.x, lane = t & 31, w = t >> 5;
    const int g = lane >> 2, t4 = lane & 3;
    const int mat = blockIdx.y;
    const int i0 = blockIdx.x * 128;
    const float* bias = (mat == 0) ? bQ : (mat == 1) ? bK : bV;

    #pragma unroll
    for (int l = 0; l < 16; l++) {
        int idx = t + l * 256;
        int r = idx >> 5, c8 = idx & 31;
        uint4 v = *(const uint4*)&g_Xbf[(size_t)(i0 + r) * DD + c8 * 8];
        *(uint4*)(sm + QX + r * 528 + c8 * 16) = v;
    }
    #pragma unroll
    for (int l = 0; l < 32; l++) {
        int idx = t + l * 256;
        int r = idx >> 5, c8 = idx & 31;
        uint4 v = *(const uint4*)&g_Wbf[mat][(size_t)r * DD + c8 * 8];
        *(uint4*)(sm + QW + r * 528 + c8 * 16) = v;
    }
    __syncthreads();

    float o[32][4];
    #pragma unroll
    for (int i = 0; i < 32; i++)
        #pragma unroll
        for (int j = 0; j < 4; j++) o[i][j] = 0.f;

    const int arow = w * 16 + (lane & 15);
    const int acol = (lane >> 4) * 8;
    const int vrow_off = ((lane >> 3) & 1) * 8 + (lane & 7);
    const int vcol_off = (lane >> 4) * 8;

    #pragma unroll
    for (int k = 0; k < 16; k++) {
        uint32_t Aa[4];
        ldm4(Aa, sb + QX + arow * 528 + (acol + k * 16) * 2);
        #pragma unroll
        for (int n16 = 0; n16 < 16; n16++) {
            uint32_t vb[4];
            ldm4t(vb, sb + QW + (k * 16 + vrow_off) * 528 + (n16 * 16 + vcol_off) * 2);
            mma16816(o[n16 * 2],     Aa, vb[0], vb[1]);
            mma16816(o[n16 * 2 + 1], Aa, vb[2], vb[3]);
        }
    }

    const int row0 = i0 + w * 16 + g;
    if (mat == 2) {
        #pragma unroll
        for (int nb = 0; nb < 32; nb++) {
            int c = nb * 8 + t4 * 2;
            float b0 = bias[c], b1 = bias[c + 1];
            *(uint32_t*)&g_Vbf[(size_t)row0 * DD + c]       = pack_bf16(o[nb][0] + b0, o[nb][1] + b1);
            *(uint32_t*)&g_Vbf[(size_t)(row0 + 8) * DD + c] = pack_bf16(o[nb][2] + b0, o[nb][3] + b1);
        }
    } else {
        uint8_t* O8 = (mat == 0) ? g_Qf8 : g_Kf8;
        #pragma unroll
        for (int nb = 0; nb < 32; nb++) {
            int c = nb * 8 + t4 * 2;
            float b0 = bias[c], b1 = bias[c + 1];
            *(uint16_t*)&O8[(size_t)row0 * DD + c]       = pack_e4m3x2(o[nb][0] + b0, o[nb][1] + b1);
            *(uint16_t*)&O8[(size_t)(row0 + 8) * DD + c] = pack_e4m3x2(o[nb][2] + b0, o[nb][3] + b1);
        }
    }
}

// ---------------------------------------------------------------------------
// K2: flash attention.  R9 ping-pong skeleton, fp8 S-phase, K double-buffered.
// 256 thr = 2 groups x 4 warps; group g: tiles g, g+2, ...
// Warp rg: S rows rg*16 x 64 keys (fp8 k32), P register-resident, AV rows x
// 256 dims (bf16).  2 barriers/iter.  Unshifted-exp softmax-one.
// ---------------------------------------------------------------------------
#define SQ    0                       // Q fp8 64 x 272 = 17408
#define SKB   17408                   // K fp8: (g*2+st)*17408, 4 bufs = 69632
#define SVB   87040                   // V bf16: g*33792, 2 bufs = 67584
#define SPKB  154624                  // pk: (g*2+st)*1024, 4 bufs = 4096
#define SRED  158720                  // m[2][64], l[2][64] = 1024
#define SMEMB 159744
// epilogue: oM f32[64][260] at sm+0 (66560); l[2][64] folded into SRED

__device__ __forceinline__ void loadK(uint32_t sb, int tg, int g, int tt)
{
    if (tt < 128) {
        const int st = (tt >> 1) & 1;
        const int j0 = tt * 64;
        const uint32_t kb = sb + SKB + (uint32_t)(g * 2 + st) * 17408;
        #pragma unroll
        for (int l = 0; l < 8; l++) {
            int idx = tg + l * 128;
            int r = idx >> 4, c16 = idx & 15;
            cp16(kb + (uint32_t)(r * 272 + c16 * 16),
                 g_Kf8 + (size_t)(j0 + r) * DD + c16 * 16);
        }
        if (tg < 64) cp16(sb + SPKB + (uint32_t)(g * 2 + st) * 1024 + tg * 16, &g_P4[j0 + tg]);
    }
    cp_commit();
}
__device__ __forceinline__ void loadV(uint32_t sb, int tg, int g, int tt)
{
    if (tt < 128) {
        const int j0 = tt * 64;
        const uint32_t vb = sb + SVB + (uint32_t)g * 33792;
        #pragma unroll
        for (int l = 0; l < 16; l++) {
            int idx = tg + l * 128;
            int r = idx >> 5, c8 = idx & 31;
            cp16(vb + (uint32_t)(r * 528 + c8 * 16),
                 (const char*)g_Vbf + ((size_t)(j0 + r) * DD + c8 * 8) * 2);
        }
    }
    cp_commit();
}

__global__ __launch_bounds__(256, 1) void flash_kernel(
    const float* __restrict__ X, float* __restrict__ out)
{
    extern __shared__ char sm[];
    const uint32_t sb = smem_u32(sm);
    const int t = threadIdx.x;
    const int lane = t & 31, w = t >> 5;
    const int rg = w & 3, g = w >> 2;       // group 0/1
    const int tg = t & 127;
    const int lg = lane >> 2, t4 = lane & 3;
    const int i0 = blockIdx.x * 64;
    const int rA = rg * 16 + lg, rB = rA + 8;
    const int barid = 1 + g;

    // stage Q fp8 (plain loads, outside commit chains)
    #pragma unroll
    for (int l = 0; l < 4; l++) {
        int idx = t + l * 256;
        int r = idx >> 4, c16 = idx & 15;
        uint4 v = *(const uint4*)&g_Qf8[(size_t)(i0 + r) * DD + c16 * 16];
        *(uint4*)(sm + SQ + r * 272 + c16 * 16) = v;
    }
    // prologue commits: [K(g)], [V(g)], [K(g+2)]
    loadK(sb, tg, g, g);
    loadV(sb, tg, g, g);
    loadK(sb, tg, g, g + 2);

    const float4 pqA = g_P4[i0 + rA];
    const float4 pqB = g_P4[i0 + rB];
    const float qAx2 = 2.f * pqA.x, qAy2 = 2.f * pqA.y, qAz2 = 2.f * pqA.z;
    const float qBx2 = 2.f * pqB.x, qBy2 = 2.f * pqB.y, qBz2 = 2.f * pqB.z;
    const float wA4 = -pqA.w - 4.0f;        // folds |pq|^2 and the /16 of scores
    const float wB4 = -pqB.w - 4.0f;
    __syncthreads();   // Q visible

    float o[32][4];
    #pragma unroll
    for (int i = 0; i < 32; i++)
        #pragma unroll
        for (int j = 0; j < 4; j++) o[i][j] = 0.f;
    float mA = -1e30f, mB = -1e30f;
    float lA = 0.f, lB = 0.f;

    const int qrow = rg * 16 + (lane & 15);
    const int qoff = (lane >> 4) * 16;                       // bytes
    const int krow_off = ((lane >> 4) << 3) + (lane & 7);
    const int kcol = ((lane >> 3) & 1) * 16;                 // bytes
    const int vrow_off = ((lane >> 3) & 1) * 8 + (lane & 7);
    const int vcol_off = (lane >> 4) * 8;
    const uint32_t vbase = sb + SVB + (uint32_t)g * 33792;
    const float L2E = 1.4426950408889634f;

    #pragma unroll 1
    for (int tt = g; tt < 128; tt += 2) {
        const int st = (tt >> 1) & 1;
        asm volatile("cp.async.wait_group 1;" ::: "memory");  // K(tt), V(tt) done
        bar_sync(barid, 128);                                  // visible to group

        // ---- S = Q K^T in fp8 : 16 rows x 64 keys, k32 steps ----
        const uint32_t kbase = sb + SKB + (uint32_t)(g * 2 + st) * 17408;
        float s[8][4];
        #pragma unroll
        for (int i = 0; i < 8; i++)
            #pragma unroll
            for (int j = 0; j < 4; j++) s[i][j] = 0.f;
        #pragma unroll
        for (int k = 0; k < 8; k++) {
            uint32_t Qa[4];
            ldm4(Qa, sb + SQ + qrow * 272 + k * 32 + qoff);
            #pragma unroll
            for (int np = 0; np < 4; np++) {
                uint32_t bf[4];
                ldm4(bf, kbase + (np * 16 + krow_off) * 272 + k * 32 + kcol);
                mma_fp8(s[np * 2],     Qa, bf[0], bf[1]);
                mma_fp8(s[np * 2 + 1], Qa, bf[2], bf[3]);
            }
        }

        // ---- decay+1/16 via single ex2; unshifted exp -> register P ----
        const float4* pk = (const float4*)(sm + SPKB + (g * 2 + st) * 1024);
        uint32_t aa[4][4];
        #pragma unroll
        for (int nb = 0; nb < 8; nb++) {
            int c0 = nb * 8 + t4 * 2;
            float4 k0 = pk[c0], k1 = pk[c0 + 1];
            float aA0 = fmaf(qAx2, k0.x, fmaf(qAy2, k0.y, fmaf(qAz2, k0.z, wA4 - k0.w)));
            float aA1 = fmaf(qAx2, k1.x, fmaf(qAy2, k1.y, fmaf(qAz2, k1.z, wA4 - k1.w)));
            float aB0 = fmaf(qBx2, k0.x, fmaf(qBy2, k0.y, fmaf(qBz2, k0.z, wB4 - k0.w)));
            float aB1 = fmaf(qBx2, k1.x, fmaf(qBy2, k1.y, fmaf(qBz2, k1.z, wB4 - k1.w)));
            float x0 = s[nb][0] * fexp2(fminf(aA0, -4.0f));
            float x1 = s[nb][1] * fexp2(fminf(aA1, -4.0f));
            float x2 = s[nb][2] * fexp2(fminf(aB0, -4.0f));
            float x3 = s[nb][3] * fexp2(fminf(aB1, -4.0f));
            mA = fmaxf(mA, fmaxf(x0, x1));
            mB = fmaxf(mB, fmaxf(x2, x3));
            float p0 = fexp2(x0 * L2E), p1 = fexp2(x1 * L2E);
            float p2 = fexp2(x2 * L2E), p3 = fexp2(x3 * L2E);
            lA += p0 + p1; lB += p2 + p3;
            if ((nb & 1) == 0) {
                aa[nb >> 1][0] = pack_bf16(p0, p1);
                aa[nb >> 1][1] = pack_bf16(p2, p3);
            } else {
                aa[nb >> 1][2] = pack_bf16(p0, p1);
                aa[nb >> 1][3] = pack_bf16(p2, p3);
            }
        }

        // ---- O += P V (bf16): 16 rows x 256 dims, 64 keys ----
        #pragma unroll
        for (int ks = 0; ks < 4; ks++) {
            #pragma unroll
            for (int n16 = 0; n16 < 16; n16++) {
                uint32_t vb[4];
                ldm4t(vb, vbase + (ks * 16 + vrow_off) * 528 + (n16 * 16 + vcol_off) * 2);
                mma16816(o[n16 * 2],     aa[ks], vb[0], vb[1]);
                mma16816(o[n16 * 2 + 1], aa[ks], vb[2], vb[3]);
            }
        }
        bar_sync(barid, 128);       // S+AV done by all -> V buf & K stage(st) free
        loadV(sb, tg, g, tt + 2);   // commit (V before K: wait_group 1 pairing)
        loadK(sb, tg, g, tt + 4);   // commit
    }

    // ---- reduce private l/m over quad lanes ----
    lA += __shfl_xor_sync(0xffffffffu, lA, 1);
    lA += __shfl_xor_sync(0xffffffffu, lA, 2);
    lB += __shfl_xor_sync(0xffffffffu, lB, 1);
    lB += __shfl_xor_sync(0xffffffffu, lB, 2);
    mA = fmaxf(mA, __shfl_xor_sync(0xffffffffu, mA, 1));
    mA = fmaxf(mA, __shfl_xor_sync(0xffffffffu, mA, 2));
    mB = fmaxf(mB, __shfl_xor_sync(0xffffffffu, mB, 1));
    mB = fmaxf(mB, __shfl_xor_sync(0xffffffffu, mB, 2));

    float* red = (float*)(sm + SRED);    // m[2][64] then l[2][64]
    if (t4 == 0) {
        red[g * 64 + rA] = mA;       red[g * 64 + rB] = mB;
        red[128 + g * 64 + rA] = lA; red[128 + g * 64 + rB] = lB;
    }
    __syncthreads();     // both groups done; K/V buffers dead -> oM overlay safe

    float* oM = (float*)sm;              // [64][260] f32 overlays Q+K region
    if (g == 1) {
        #pragma unroll
        for (int nb = 0; nb < 32; nb++) {
            int c = nb * 8 + t4 * 2;
            oM[rA * 260 + c] = o[nb][0]; oM[rA * 260 + c + 1] = o[nb][1];
            oM[rB * 260 + c] = o[nb][2]; oM[rB * 260 + c + 1] = o[nb][3];
        }
    }
    __syncthreads();
    if (g == 0) {
        float MA = fmaxf(red[rA], red[64 + rA]);
        float MB = fmaxf(red[rB], red[64 + rB]);
        float invA = 1.f / (fexp2(MA * L2E) + red[128 + rA] + red[192 + rA]);
        float invB = 1.f / (fexp2(MB * L2E) + red[128 + rB] + red[192 + rB]);
        const int gA = i0 + rA, gB = i0 + rB;
        #pragma unroll
        for (int nb = 0; nb < 32; nb++) {
            int c = nb * 8 + t4 * 2;
            float2 vA, vB;
            vA.x = (o[nb][0] + oM[rA * 260 + c])     * invA + X[(size_t)gA * XSTR + c];
            vA.y = (o[nb][1] + oM[rA * 260 + c + 1]) * invA + X[(size_t)gA * XSTR + c + 1];
            vB.x = (o[nb][2] + oM[rB * 260 + c])     * invB + X[(size_t)gB * XSTR + c];
            vB.y = (o[nb][3] + oM[rB * 260 + c + 1]) * invB + X[(size_t)gB * XSTR + c + 1];
            *(float2*)&out[(size_t)gA * DD + c] = vA;
            *(float2*)&out[(size_t)gB * DD + c] = vB;
        }
    }
}

// ---------------------------------------------------------------------------
extern "C" void kernel_launch(void* const* d_in, const int* in_sizes, int n_in,
                              void* d_out, int out_size)
{
    const float* X  = (const float*)d_in[0];
    const float* WQ = (const float*)d_in[1];
    const float* bQ = (const float*)d_in[2];
    const float* WK = (const float*)d_in[3];
    const float* bK = (const float*)d_in[4];
    const float* WV = (const float*)d_in[5];
    const float* bV = (const float*)d_in[6];
    float* out = (float*)d_out;

    cudaFuncSetAttribute(flash_kernel, cudaFuncAttributeMaxDynamicSharedMemorySize, SMEMB);
    cudaFuncSetAttribute(qkv_mma_kernel, cudaFuncAttributeMaxDynamicSharedMemorySize, SMEMQ);

    prep_kernel<<<NN * 32 / 256, 256>>>(X);
    wconv_kernel<<<dim3(DD * DD / 8 / 256, 3), 256>>>(WQ, WK, WV);
    qkv_mma_kernel<<<dim3(NN / 128, 3), 256, SMEMQ>>>(bQ, bK, bV);
    flash_kernel<<<NN / 64, 256, SMEMB>>>(X, out);
}

// round 14
// speedup vs baseline: 1.3976x; 1.0044x over previous
#include <cuda_runtime.h>
#include <cuda_bf16.h>
#include <cuda_fp16.h>
#include <cstdint>

#define NN 8192
#define DD 256
#define XSTR 259

// ---------------- device scratch ----------------
__device__ __nv_bfloat16 g_Xbf[NN * DD];
__device__ __nv_bfloat16 g_Wbf[3][DD * DD];
__device__ uint8_t g_Qf8[NN * DD];            // Q e4m3 (UNSCALED; /16 folded into decay)
__device__ uint8_t g_Kf8[NN * DD];            // K e4m3
__device__ __half  g_Vhf[NN * DD];            // V f16
__device__ float4 g_P4[NN];   // scaled: (c*px, c*py, c*pz, c^2*|p|^2), c^2 = 0.5*log2(e)

// ---------------- helpers ----------------
__device__ __forceinline__ uint32_t smem_u32(const void* p) {
    uint32_t a;
    asm("{ .reg .u64 t; cvta.to.shared.u64 t, %1; cvt.u32.u64 %0, t; }" : "=r"(a) : "l"(p));
    return a;
}
__device__ __forceinline__ float fexp2(float x) {
    float r;
    asm("ex2.approx.f32 %0, %1;" : "=f"(r) : "f"(x));
    return r;
}
__device__ __forceinline__ uint32_t pack_bf16(float lo, float hi) {
    uint32_t r;
    asm("cvt.rn.bf16x2.f32 %0, %1, %2;" : "=r"(r) : "f"(hi), "f"(lo));
    return r;
}
__device__ __forceinline__ uint32_t pack_f16(float lo, float hi) {
    uint32_t r;
    asm("cvt.rn.f16x2.f32 %0, %1, %2;" : "=r"(r) : "f"(hi), "f"(lo));
    return r;
}
__device__ __forceinline__ uint16_t pack_e4m3x2(float lo, float hi) {
    uint16_t r;
    asm("cvt.rn.satfinite.e4m3x2.f32 %0, %1, %2;" : "=h"(r) : "f"(hi), "f"(lo));
    return r;
}
__device__ __forceinline__ void cp16(uint32_t s, const void* g) {
    asm volatile("cp.async.cg.shared.global [%0], [%1], 16;" :: "r"(s), "l"(g));
}
__device__ __forceinline__ void cp_commit() {
    asm volatile("cp.async.commit_group;" ::: "memory");
}
__device__ __forceinline__ void ldm4(uint32_t* r, uint32_t a) {
    asm volatile("ldmatrix.sync.aligned.m8n8.x4.shared.b16 {%0,%1,%2,%3}, [%4];"
                 : "=r"(r[0]), "=r"(r[1]), "=r"(r[2]), "=r"(r[3]) : "r"(a));
}
__device__ __forceinline__ void ldm4t(uint32_t* r, uint32_t a) {
    asm volatile("ldmatrix.sync.aligned.m8n8.x4.trans.shared.b16 {%0,%1,%2,%3}, [%4];"
                 : "=r"(r[0]), "=r"(r[1]), "=r"(r[2]), "=r"(r[3]) : "r"(a));
}
__device__ __forceinline__ void mma16816(float* c, const uint32_t* a, uint32_t b0, uint32_t b1) {
    asm volatile(
        "mma.sync.aligned.m16n8k16.row.col.f32.bf16.bf16.f32 "
        "{%0,%1,%2,%3}, {%4,%5,%6,%7}, {%8,%9}, {%0,%1,%2,%3};"
        : "+f"(c[0]), "+f"(c[1]), "+f"(c[2]), "+f"(c[3])
        : "r"(a[0]), "r"(a[1]), "r"(a[2]), "r"(a[3]), "r"(b0), "r"(b1));
}
__device__ __forceinline__ void mma_fp8(float* c, const uint32_t* a, uint32_t b0, uint32_t b1) {
    asm volatile(
        "mma.sync.aligned.m16n8k32.row.col.f32.e4m3.e4m3.f32 "
        "{%0,%1,%2,%3}, {%4,%5,%6,%7}, {%8,%9}, {%0,%1,%2,%3};"
        : "+f"(c[0]), "+f"(c[1]), "+f"(c[2]), "+f"(c[3])
        : "r"(a[0]), "r"(a[1]), "r"(a[2]), "r"(a[3]), "r"(b0), "r"(b1));
}
__device__ __forceinline__ void mma_h16(uint32_t* c, const uint32_t* a, uint32_t b0, uint32_t b1) {
    asm volatile(
        "mma.sync.aligned.m16n8k16.row.col.f16.f16.f16.f16 "
        "{%0,%1}, {%2,%3,%4,%5}, {%6,%7}, {%0,%1};"
        : "+r"(c[0]), "+r"(c[1])
        : "r"(a[0]), "r"(a[1]), "r"(a[2]), "r"(a[3]), "r"(b0), "r"(b1));
}
__device__ __forceinline__ void bar_sync(int id, int cnt) {
    asm volatile("bar.sync %0, %1;" :: "r"(id), "r"(cnt) : "memory");
}

// ---------------------------------------------------------------------------
// K0: prep — X -> bf16, scaled positions (X rows only 4B-aligned: scalar loads)
// ---------------------------------------------------------------------------
__global__ __launch_bounds__(256) void prep_kernel(const float* __restrict__ X)
{
    int idx = blockIdx.x * 256 + threadIdx.x;
    int row = idx >> 5, c8 = idx & 31;
    const float* xr = X + (size_t)row * XSTR + c8 * 8;
    float v0 = xr[0], v1 = xr[1], v2 = xr[2], v3 = xr[3];
    float v4 = xr[4], v5 = xr[5], v6 = xr[6], v7 = xr[7];
    uint4 u;
    u.x = pack_bf16(v0, v1); u.y = pack_bf16(v2, v3);
    u.z = pack_bf16(v4, v5); u.w = pack_bf16(v6, v7);
    *(uint4*)&g_Xbf[(size_t)row * DD + c8 * 8] = u;
    if (c8 == 0) {
        const float c = 0.84932180f;          // sqrt(0.5*log2(e))
        float px = X[(size_t)row * XSTR + 256] * c;
        float py = X[(size_t)row * XSTR + 257] * c;
        float pz = X[(size_t)row * XSTR + 258] * c;
        g_P4[row] = make_float4(px, py, pz, px*px + py*py + pz*pz);
    }
}

// ---------------------------------------------------------------------------
// K0b: W -> bf16 (no scaling; /16 folded into decay exponent)
// ---------------------------------------------------------------------------
__global__ __launch_bounds__(256) void wconv_kernel(
    const float* __restrict__ WQ, const float* __restrict__ WK, const float* __restrict__ WV)
{
    int mat = blockIdx.y;
    const float* W = (mat == 0) ? WQ : (mat == 1) ? WK : WV;
    int idx = blockIdx.x * 256 + threadIdx.x;
    int base = idx * 8;
    const float4* wr = (const float4*)(W + base);
    float4 a = wr[0], b = wr[1];
    uint4 u;
    u.x = pack_bf16(a.x, a.y); u.y = pack_bf16(a.z, a.w);
    u.z = pack_bf16(b.x, b.y); u.w = pack_bf16(b.z, b.w);
    *(uint4*)&g_Wbf[mat][base] = u;
}

// ---------------------------------------------------------------------------
// K1: QKV via mma.sync.  grid (64, 3), 256 thr.  Q/K -> e4m3, V -> f16.
// ---------------------------------------------------------------------------
#define QX 0
#define QW 67584
#define SMEMQ (67584 + 135168)

__global__ __launch_bounds__(256, 1) void qkv_mma_kernel(
    const float* __restrict__ bQ, const float* __restrict__ bK, const float* __restrict__ bV)
{
    extern __shared__ char sm[];
    const uint32_t sb = smem_u32(sm);
    const int t = threadIdx.x, lane = t & 31, w = t >> 5;
    const int g = lane >> 2, t4 = lane & 3;
    const int mat = blockIdx.y;
    const int i0 = blockIdx.x * 128;
    const float* bias = (mat == 0) ? bQ : (mat == 1) ? bK : bV;

    #pragma unroll
    for (int l = 0; l < 16; l++) {
        int idx = t + l * 256;
        int r = idx >> 5, c8 = idx & 31;
        uint4 v = *(const uint4*)&g_Xbf[(size_t)(i0 + r) * DD + c8 * 8];
        *(uint4*)(sm + QX + r * 528 + c8 * 16) = v;
    }
    #pragma unroll
    for (int l = 0; l < 32; l++) {
        int idx = t + l * 256;
        int r = idx >> 5, c8 = idx & 31;
        uint4 v = *(const uint4*)&g_Wbf[mat][(size_t)r * DD + c8 * 8];
        *(uint4*)(sm + QW + r * 528 + c8 * 16) = v;
    }
    __syncthreads();

    float o[32][4];
    #pragma unroll
    for (int i = 0; i < 32; i++)
        #pragma unroll
        for (int j = 0; j < 4; j++) o[i][j] = 0.f;

    const int arow = w * 16 + (lane & 15);
    const int acol = (lane >> 4) * 8;
    const int vrow_off = ((lane >> 3) & 1) * 8 + (lane & 7);
    const int vcol_off = (lane >> 4) * 8;

    #pragma unroll
    for (int k = 0; k < 16; k++) {
        uint32_t Aa[4];
        ldm4(Aa, sb + QX + arow * 528 + (acol + k * 16) * 2);
        #pragma unroll
        for (int n16 = 0; n16 < 16; n16++) {
            uint32_t vb[4];
            ldm4t(vb, sb + QW + (k * 16 + vrow_off) * 528 + (n16 * 16 + vcol_off) * 2);
            mma16816(o[n16 * 2],     Aa, vb[0], vb[1]);
            mma16816(o[n16 * 2 + 1], Aa, vb[2], vb[3]);
        }
    }

    const int row0 = i0 + w * 16 + g;
    if (mat == 2) {
        #pragma unroll
        for (int nb = 0; nb < 32; nb++) {
            int c = nb * 8 + t4 * 2;
            float b0 = bias[c], b1 = bias[c + 1];
            *(uint32_t*)&g_Vhf[(size_t)row0 * DD + c]       = pack_f16(o[nb][0] + b0, o[nb][1] + b1);
            *(uint32_t*)&g_Vhf[(size_t)(row0 + 8) * DD + c] = pack_f16(o[nb][2] + b0, o[nb][3] + b1);
        }
    } else {
        uint8_t* O8 = (mat == 0) ? g_Qf8 : g_Kf8;
        #pragma unroll
        for (int nb = 0; nb < 32; nb++) {
            int c = nb * 8 + t4 * 2;
            float b0 = bias[c], b1 = bias[c + 1];
            *(uint16_t*)&O8[(size_t)row0 * DD + c]       = pack_e4m3x2(o[nb][0] + b0, o[nb][1] + b1);
            *(uint16_t*)&O8[(size_t)(row0 + 8) * DD + c] = pack_e4m3x2(o[nb][2] + b0, o[nb][3] + b1);
        }
    }
}

// ---------------------------------------------------------------------------
// K2: flash attention.  fp8 S (K double-buffered) + f16 AV with f16 acc.
// 256 thr = 2 ping-pong groups x 4 warps; group g: tiles g, g+2, ...
// Warp rg: S rows rg*16 x 64 keys (fp8 k32, Qa hoisted), P register-resident
// (f16), AV rows x 256 dims (f16 acc, 2-reg C).  2 barriers/iter.
// Unshifted-exp softmax-one.
// ---------------------------------------------------------------------------
#define SQ    0                       // Q fp8 64 x 272 = 17408
#define SKB   17408                   // K fp8: (g*2+st)*17408, 4 bufs = 69632
#define SVB   87040                   // V f16: g*33792, 2 bufs = 67584
#define SPKB  154624                  // pk: (g*2+st)*1024, 4 bufs = 4096
#define SRED  158720                  // m[2][64], l[2][64] = 1024
#define SMEMB 159744
// epilogue: oM f32[64][260] at sm+0 (66560)

__device__ __forceinline__ void loadK(uint32_t sb, int tg, int g, int tt)
{
    if (tt < 128) {
        const int st = (tt >> 1) & 1;
        const int j0 = tt * 64;
        const uint32_t kb = sb + SKB + (uint32_t)(g * 2 + st) * 17408;
        #pragma unroll
        for (int l = 0; l < 8; l++) {
            int idx = tg + l * 128;
            int r = idx >> 4, c16 = idx & 15;
            cp16(kb + (uint32_t)(r * 272 + c16 * 16),
                 g_Kf8 + (size_t)(j0 + r) * DD + c16 * 16);
        }
        if (tg < 64) cp16(sb + SPKB + (uint32_t)(g * 2 + st) * 1024 + tg * 16, &g_P4[j0 + tg]);
    }
    cp_commit();
}
__device__ __forceinline__ void loadV(uint32_t sb, int tg, int g, int tt)
{
    if (tt < 128) {
        const int j0 = tt * 64;
        const uint32_t vb = sb + SVB + (uint32_t)g * 33792;
        #pragma unroll
        for (int l = 0; l < 16; l++) {
            int idx = tg + l * 128;
            int r = idx >> 5, c8 = idx & 31;
            cp16(vb + (uint32_t)(r * 528 + c8 * 16),
                 (const char*)g_Vhf + ((size_t)(j0 + r) * DD + c8 * 8) * 2);
        }
    }
    cp_commit();
}

__global__ __launch_bounds__(256, 1) void flash_kernel(
    const float* __restrict__ X, float* __restrict__ out)
{
    extern __shared__ char sm[];
    const uint32_t sb = smem_u32(sm);
    const int t = threadIdx.x;
    const int lane = t & 31, w = t >> 5;
    const int rg = w & 3, g = w >> 2;       // group 0/1
    const int tg = t & 127;
    const int lg = lane >> 2, t4 = lane & 3;
    const int i0 = blockIdx.x * 64;
    const int rA = rg * 16 + lg, rB = rA + 8;
    const int barid = 1 + g;

    // stage Q fp8
    #pragma unroll
    for (int l = 0; l < 4; l++) {
        int idx = t + l * 256;
        int r = idx >> 4, c16 = idx & 15;
        uint4 v = *(const uint4*)&g_Qf8[(size_t)(i0 + r) * DD + c16 * 16];
        *(uint4*)(sm + SQ + r * 272 + c16 * 16) = v;
    }
    // prologue commits: [K(g)], [V(g)], [K(g+2)]
    loadK(sb, tg, g, g);
    loadV(sb, tg, g, g);
    loadK(sb, tg, g, g + 2);

    const float4 pqA = g_P4[i0 + rA];
    const float4 pqB = g_P4[i0 + rB];
    const float qAx2 = 2.f * pqA.x, qAy2 = 2.f * pqA.y, qAz2 = 2.f * pqA.z;
    const float qBx2 = 2.f * pqB.x, qBy2 = 2.f * pqB.y, qBz2 = 2.f * pqB.z;
    const float wA4 = -pqA.w - 4.0f;        // folds |pq|^2 and the /16 of scores
    const float wB4 = -pqB.w - 4.0f;
    __syncthreads();   // Q visible

    // hoist Q fragments (tile-invariant): 8 k-steps x 4 regs
    const int qrow = rg * 16 + (lane & 15);
    const int qoff = (lane >> 4) * 16;                       // bytes
    uint32_t Qa[8][4];
    #pragma unroll
    for (int k = 0; k < 8; k++)
        ldm4(Qa[k], sb + SQ + qrow * 272 + k * 32 + qoff);

    uint32_t o[32][2];                     // f16x2 accumulators
    #pragma unroll
    for (int i = 0; i < 32; i++) { o[i][0] = 0u; o[i][1] = 0u; }
    float mA = -1e30f, mB = -1e30f;
    float lA = 0.f, lB = 0.f;

    const int krow_off = ((lane >> 4) << 3) + (lane & 7);
    const int kcol = ((lane >> 3) & 1) * 16;                 // bytes
    const int vrow_off = ((lane >> 3) & 1) * 8 + (lane & 7);
    const int vcol_off = (lane >> 4) * 8;
    const uint32_t vbase = sb + SVB + (uint32_t)g * 33792;
    const float L2E = 1.4426950408889634f;

    #pragma unroll 1
    for (int tt = g; tt < 128; tt += 2) {
        const int st = (tt >> 1) & 1;
        asm volatile("cp.async.wait_group 1;" ::: "memory");  // K(tt), V(tt) done
        bar_sync(barid, 128);                                  // visible to group

        // ---- S = Q K^T in fp8 : 16 rows x 64 keys, k32 steps ----
        const uint32_t kbase = sb + SKB + (uint32_t)(g * 2 + st) * 17408;
        float s[8][4];
        #pragma unroll
        for (int i = 0; i < 8; i++)
            #pragma unroll
            for (int j = 0; j < 4; j++) s[i][j] = 0.f;
        #pragma unroll
        for (int k = 0; k < 8; k++) {
            #pragma unroll
            for (int np = 0; np < 4; np++) {
                uint32_t bf[4];
                ldm4(bf, kbase + (np * 16 + krow_off) * 272 + k * 32 + kcol);
                mma_fp8(s[np * 2],     Qa[k], bf[0], bf[1]);
                mma_fp8(s[np * 2 + 1], Qa[k], bf[2], bf[3]);
            }
        }

        // ---- decay+1/16 via single ex2; unshifted exp -> register P (f16) ----
        const float4* pk = (const float4*)(sm + SPKB + (g * 2 + st) * 1024);
        uint32_t aa[4][4];
        #pragma unroll
        for (int nb = 0; nb < 8; nb++) {
            int c0 = nb * 8 + t4 * 2;
            float4 k0 = pk[c0], k1 = pk[c0 + 1];
            float aA0 = fmaf(qAx2, k0.x, fmaf(qAy2, k0.y, fmaf(qAz2, k0.z, wA4 - k0.w)));
            float aA1 = fmaf(qAx2, k1.x, fmaf(qAy2, k1.y, fmaf(qAz2, k1.z, wA4 - k1.w)));
            float aB0 = fmaf(qBx2, k0.x, fmaf(qBy2, k0.y, fmaf(qBz2, k0.z, wB4 - k0.w)));
            float aB1 = fmaf(qBx2, k1.x, fmaf(qBy2, k1.y, fmaf(qBz2, k1.z, wB4 - k1.w)));
            float x0 = s[nb][0] * fexp2(fminf(aA0, -4.0f));
            float x1 = s[nb][1] * fexp2(fminf(aA1, -4.0f));
            float x2 = s[nb][2] * fexp2(fminf(aB0, -4.0f));
            float x3 = s[nb][3] * fexp2(fminf(aB1, -4.0f));
            mA = fmaxf(mA, fmaxf(x0, x1));
            mB = fmaxf(mB, fmaxf(x2, x3));
            float p0 = fexp2(x0 * L2E), p1 = fexp2(x1 * L2E);
            float p2 = fexp2(x2 * L2E), p3 = fexp2(x3 * L2E);
            lA += p0 + p1; lB += p2 + p3;
            if ((nb & 1) == 0) {
                aa[nb >> 1][0] = pack_f16(p0, p1);
                aa[nb >> 1][1] = pack_f16(p2, p3);
            } else {
                aa[nb >> 1][2] = pack_f16(p0, p1);
                aa[nb >> 1][3] = pack_f16(p2, p3);
            }
        }

        // ---- O += P V (f16 acc): 16 rows x 256 dims, 64 keys ----
        #pragma unroll
        for (int ks = 0; ks < 4; ks++) {
            #pragma unroll
            for (int n16 = 0; n16 < 16; n16++) {
                uint32_t vb[4];
                ldm4t(vb, vbase + (ks * 16 + vrow_off) * 528 + (n16 * 16 + vcol_off) * 2);
                mma_h16(o[n16 * 2],     aa[ks], vb[0], vb[1]);
                mma_h16(o[n16 * 2 + 1], aa[ks], vb[2], vb[3]);
            }
        }
        bar_sync(barid, 128);       // S+AV done -> V buf & K stage(st) free
        loadV(sb, tg, g, tt + 2);
        loadK(sb, tg, g, tt + 4);
    }

    // ---- reduce private l/m over quad lanes ----
    lA += __shfl_xor_sync(0xffffffffu, lA, 1);
    lA += __shfl_xor_sync(0xffffffffu, lA, 2);
    lB += __shfl_xor_sync(0xffffffffu, lB, 1);
    lB += __shfl_xor_sync(0xffffffffu, lB, 2);
    mA = fmaxf(mA, __shfl_xor_sync(0xffffffffu, mA, 1));
    mA = fmaxf(mA, __shfl_xor_sync(0xffffffffu, mA, 2));
    mB = fmaxf(mB, __shfl_xor_sync(0xffffffffu, mB, 1));
    mB = fmaxf(mB, __shfl_xor_sync(0xffffffffu, mB, 2));

    float* red = (float*)(sm + SRED);    // m[2][64] then l[2][64]
    if (t4 == 0) {
        red[g * 64 + rA] = mA;       red[g * 64 + rB] = mB;
        red[128 + g * 64 + rA] = lA; red[128 + g * 64 + rB] = lB;
    }
    __syncthreads();     // both groups done; K/V buffers dead -> oM overlay safe

    float* oM = (float*)sm;              // [64][260] f32 overlays Q+K region
    if (g == 1) {
        #pragma unroll
        for (int nb = 0; nb < 32; nb++) {
            int c = nb * 8 + t4 * 2;
            float2 fA = __half22float2(*reinterpret_cast<const __half2*>(&o[nb][0]));
            float2 fB = __half22float2(*reinterpret_cast<const __half2*>(&o[nb][1]));
            oM[rA * 260 + c] = fA.x; oM[rA * 260 + c + 1] = fA.y;
            oM[rB * 260 + c] = fB.x; oM[rB * 260 + c + 1] = fB.y;
        }
    }
    __syncthreads();
    if (g == 0) {
        float MA = fmaxf(red[rA], red[64 + rA]);
        float MB = fmaxf(red[rB], red[64 + rB]);
        float invA = 1.f / (fexp2(MA * L2E) + red[128 + rA] + red[192 + rA]);
        float invB = 1.f / (fexp2(MB * L2E) + red[128 + rB] + red[192 + rB]);
        const int gA = i0 + rA, gB = i0 + rB;
        #pragma unroll
        for (int nb = 0; nb < 32; nb++) {
            int c = nb * 8 + t4 * 2;
            float2 fA = __half22float2(*reinterpret_cast<const __half2*>(&o[nb][0]));
            float2 fB = __half22float2(*reinterpret_cast<const __half2*>(&o[nb][1]));
            float2 vA, vB;
            vA.x = (fA.x + oM[rA * 260 + c])     * invA + X[(size_t)gA * XSTR + c];
            vA.y = (fA.y + oM[rA * 260 + c + 1]) * invA + X[(size_t)gA * XSTR + c + 1];
            vB.x = (fB.x + oM[rB * 260 + c])     * invB + X[(size_t)gB * XSTR + c];
            vB.y = (fB.y + oM[rB * 260 + c + 1]) * invB + X[(size_t)gB * XSTR + c + 1];
            *(float2*)&out[(size_t)gA * DD + c] = vA;
            *(float2*)&out[(size_t)gB * DD + c] = vB;
        }
    }
}

// ---------------------------------------------------------------------------
extern "C" void kernel_launch(void* const* d_in, const int* in_sizes, int n_in,
                              void* d_out, int out_size)
{
    const float* X  = (const float*)d_in[0];
    const float* WQ = (const float*)d_in[1];
    const float* bQ = (const float*)d_in[2];
    const float* WK = (const float*)d_in[3];
    const float* bK = (const float*)d_in[4];
    const float* WV = (const float*)d_in[5];
    const float* bV = (const float*)d_in[6];
    float* out = (float*)d_out;

    cudaFuncSetAttribute(flash_kernel, cudaFuncAttributeMaxDynamicSharedMemorySize, SMEMB);
    cudaFuncSetAttribute(qkv_mma_kernel, cudaFuncAttributeMaxDynamicSharedMemorySize, SMEMQ);

    prep_kernel<<<NN * 32 / 256, 256>>>(X);
    wconv_kernel<<<dim3(DD * DD / 8 / 256, 3), 256>>>(WQ, WK, WV);
    qkv_mma_kernel<<<dim3(NN / 128, 3), 256, SMEMQ>>>(bQ, bK, bV);
    flash_kernel<<<NN / 64, 256, SMEMB>>>(X, out);
}

// round 15
// speedup vs baseline: 1.5430x; 1.1040x over previous
#include <cuda_runtime.h>
#include <cuda_bf16.h>
#include <cuda_fp16.h>
#include <cstdint>

#define NN 8192
#define DD 256
#define XSTR 259

// ---------------- device scratch ----------------
__device__ __nv_bfloat16 g_Xbf[NN * DD];
__device__ __nv_bfloat16 g_Wbf[3][DD * DD];
__device__ uint8_t g_Qf8[NN * DD];            // Q e4m3, scaled by L2E (log2-domain scores)
__device__ uint8_t g_Kf8[NN * DD];            // K e4m3
__device__ __half  g_Vhf[NN * DD];            // V f16
__device__ __half  g_Pq[NN * 16];             // decay A-features per row
__device__ __half  g_Pk[NN * 16];             // decay B-features per key

// ---------------- helpers ----------------
__device__ __forceinline__ uint32_t smem_u32(const void* p) {
    uint32_t a;
    asm("{ .reg .u64 t; cvta.to.shared.u64 t, %1; cvt.u32.u64 %0, t; }" : "=r"(a) : "l"(p));
    return a;
}
__device__ __forceinline__ float fexp2(float x) {
    float r;
    asm("ex2.approx.f32 %0, %1;" : "=f"(r) : "f"(x));
    return r;
}
__device__ __forceinline__ uint32_t pack_bf16(float lo, float hi) {
    uint32_t r;
    asm("cvt.rn.bf16x2.f32 %0, %1, %2;" : "=r"(r) : "f"(hi), "f"(lo));
    return r;
}
__device__ __forceinline__ uint32_t pack_f16(float lo, float hi) {
    uint32_t r;
    asm("cvt.rn.f16x2.f32 %0, %1, %2;" : "=r"(r) : "f"(hi), "f"(lo));
    return r;
}
__device__ __forceinline__ uint16_t pack_e4m3x2(float lo, float hi) {
    uint16_t r;
    asm("cvt.rn.satfinite.e4m3x2.f32 %0, %1, %2;" : "=h"(r) : "f"(hi), "f"(lo));
    return r;
}
__device__ __forceinline__ void cp16(uint32_t s, const void* g) {
    asm volatile("cp.async.cg.shared.global [%0], [%1], 16;" :: "r"(s), "l"(g));
}
__device__ __forceinline__ void cp_commit() {
    asm volatile("cp.async.commit_group;" ::: "memory");
}
__device__ __forceinline__ void ldm4(uint32_t* r, uint32_t a) {
    asm volatile("ldmatrix.sync.aligned.m8n8.x4.shared.b16 {%0,%1,%2,%3}, [%4];"
                 : "=r"(r[0]), "=r"(r[1]), "=r"(r[2]), "=r"(r[3]) : "r"(a));
}
__device__ __forceinline__ void ldm4t(uint32_t* r, uint32_t a) {
    asm volatile("ldmatrix.sync.aligned.m8n8.x4.trans.shared.b16 {%0,%1,%2,%3}, [%4];"
                 : "=r"(r[0]), "=r"(r[1]), "=r"(r[2]), "=r"(r[3]) : "r"(a));
}
__device__ __forceinline__ void mma16816(float* c, const uint32_t* a, uint32_t b0, uint32_t b1) {
    asm volatile(
        "mma.sync.aligned.m16n8k16.row.col.f32.bf16.bf16.f32 "
        "{%0,%1,%2,%3}, {%4,%5,%6,%7}, {%8,%9}, {%0,%1,%2,%3};"
        : "+f"(c[0]), "+f"(c[1]), "+f"(c[2]), "+f"(c[3])
        : "r"(a[0]), "r"(a[1]), "r"(a[2]), "r"(a[3]), "r"(b0), "r"(b1));
}
__device__ __forceinline__ void mma16816h(float* c, const uint32_t* a, uint32_t b0, uint32_t b1) {
    asm volatile(
        "mma.sync.aligned.m16n8k16.row.col.f32.f16.f16.f32 "
        "{%0,%1,%2,%3}, {%4,%5,%6,%7}, {%8,%9}, {%0,%1,%2,%3};"
        : "+f"(c[0]), "+f"(c[1]), "+f"(c[2]), "+f"(c[3])
        : "r"(a[0]), "r"(a[1]), "r"(a[2]), "r"(a[3]), "r"(b0), "r"(b1));
}
__device__ __forceinline__ void mma_fp8(float* c, const uint32_t* a, uint32_t b0, uint32_t b1) {
    asm volatile(
        "mma.sync.aligned.m16n8k32.row.col.f32.e4m3.e4m3.f32 "
        "{%0,%1,%2,%3}, {%4,%5,%6,%7}, {%8,%9}, {%0,%1,%2,%3};"
        : "+f"(c[0]), "+f"(c[1]), "+f"(c[2]), "+f"(c[3])
        : "r"(a[0]), "r"(a[1]), "r"(a[2]), "r"(a[3]), "r"(b0), "r"(b1));
}
__device__ __forceinline__ void mma_h16(uint32_t* c, const uint32_t* a, uint32_t b0, uint32_t b1) {
    asm volatile(
        "mma.sync.aligned.m16n8k16.row.col.f16.f16.f16.f16 "
        "{%0,%1}, {%2,%3,%4,%5}, {%6,%7}, {%0,%1};"
        : "+r"(c[0]), "+r"(c[1])
        : "r"(a[0]), "r"(a[1]), "r"(a[2]), "r"(a[3]), "r"(b0), "r"(b1));
}
__device__ __forceinline__ void bar_sync(int id, int cnt) {
    asm volatile("bar.sync %0, %1;" :: "r"(id), "r"(cnt) : "memory");
}

// ---------------------------------------------------------------------------
// K0: prep — X -> bf16, decay feature rows (X rows only 4B-aligned: scalar)
// ---------------------------------------------------------------------------
__global__ __launch_bounds__(256) void prep_kernel(const float* __restrict__ X)
{
    int idx = blockIdx.x * 256 + threadIdx.x;
    int row = idx >> 5, c8 = idx & 31;
    const float* xr = X + (size_t)row * XSTR + c8 * 8;
    float v0 = xr[0], v1 = xr[1], v2 = xr[2], v3 = xr[3];
    float v4 = xr[4], v5 = xr[5], v6 = xr[6], v7 = xr[7];
    uint4 u;
    u.x = pack_bf16(v0, v1); u.y = pack_bf16(v2, v3);
    u.z = pack_bf16(v4, v5); u.w = pack_bf16(v6, v7);
    *(uint4*)&g_Xbf[(size_t)row * DD + c8 * 8] = u;
    if (c8 == 0) {
        const float c2 = 0.72134752f;   // 0.5 * log2(e)
        float px = X[(size_t)row * XSTR + 256];
        float py = X[(size_t)row * XSTR + 257];
        float pz = X[(size_t)row * XSTR + 258];
        float n2 = px*px + py*py + pz*pz;
        // Qp = [2c2*px, 2c2*py, 2c2*pz, -(c2*n2+4), 1, 0...]
        uint4 q0;
        q0.x = pack_f16(2.f*c2*px, 2.f*c2*py);
        q0.y = pack_f16(2.f*c2*pz, -(c2*n2 + 4.f));
        q0.z = pack_f16(1.f, 0.f);
        q0.w = 0u;
        *(uint4*)&g_Pq[row * 16]     = q0;
        *(uint4*)&g_Pq[row * 16 + 8] = make_uint4(0u, 0u, 0u, 0u);
        // Kp = [px, py, pz, 1, -c2*n2, 0...]
        uint4 k0;
        k0.x = pack_f16(px, py);
        k0.y = pack_f16(pz, 1.f);
        k0.z = pack_f16(-c2*n2, 0.f);
        k0.w = 0u;
        *(uint4*)&g_Pk[row * 16]     = k0;
        *(uint4*)&g_Pk[row * 16 + 8] = make_uint4(0u, 0u, 0u, 0u);
    }
}

// ---------------------------------------------------------------------------
// K0b: W -> bf16
// ---------------------------------------------------------------------------
__global__ __launch_bounds__(256) void wconv_kernel(
    const float* __restrict__ WQ, const float* __restrict__ WK, const float* __restrict__ WV)
{
    int mat = blockIdx.y;
    const float* W = (mat == 0) ? WQ : (mat == 1) ? WK : WV;
    int idx = blockIdx.x * 256 + threadIdx.x;
    int base = idx * 8;
    const float4* wr = (const float4*)(W + base);
    float4 a = wr[0], b = wr[1];
    uint4 u;
    u.x = pack_bf16(a.x, a.y); u.y = pack_bf16(a.z, a.w);
    u.z = pack_bf16(b.x, b.y); u.w = pack_bf16(b.z, b.w);
    *(uint4*)&g_Wbf[mat][base] = u;
}

// ---------------------------------------------------------------------------
// K1: QKV via mma.sync.  Q -> e4m3 * L2E, K -> e4m3, V -> f16.
// ---------------------------------------------------------------------------
#define QX 0
#define QW 67584
#define SMEMQ (67584 + 135168)

__global__ __launch_bounds__(256, 1) void qkv_mma_kernel(
    const float* __restrict__ bQ, const float* __restrict__ bK, const float* __restrict__ bV)
{
    extern __shared__ char sm[];
    const uint32_t sb = smem_u32(sm);
    const int t = threadIdx.x, lane = t & 31, w = t >> 5;
    const int g = lane >> 2, t4 = lane & 3;
    const int mat = blockIdx.y;
    const int i0 = blockIdx.x * 128;
    const float* bias = (mat == 0) ? bQ : (mat == 1) ? bK : bV;

    #pragma unroll
    for (int l = 0; l < 16; l++) {
        int idx = t + l * 256;
        int r = idx >> 5, c8 = idx & 31;
        uint4 v = *(const uint4*)&g_Xbf[(size_t)(i0 + r) * DD + c8 * 8];
        *(uint4*)(sm + QX + r * 528 + c8 * 16) = v;
    }
    #pragma unroll
    for (int l = 0; l < 32; l++) {
        int idx = t + l * 256;
        int r = idx >> 5, c8 = idx & 31;
        uint4 v = *(const uint4*)&g_Wbf[mat][(size_t)r * DD + c8 * 8];
        *(uint4*)(sm + QW + r * 528 + c8 * 16) = v;
    }
    __syncthreads();

    float o[32][4];
    #pragma unroll
    for (int i = 0; i < 32; i++)
        #pragma unroll
        for (int j = 0; j < 4; j++) o[i][j] = 0.f;

    const int arow = w * 16 + (lane & 15);
    const int acol = (lane >> 4) * 8;
    const int vrow_off = ((lane >> 3) & 1) * 8 + (lane & 7);
    const int vcol_off = (lane >> 4) * 8;

    #pragma unroll
    for (int k = 0; k < 16; k++) {
        uint32_t Aa[4];
        ldm4(Aa, sb + QX + arow * 528 + (acol + k * 16) * 2);
        #pragma unroll
        for (int n16 = 0; n16 < 16; n16++) {
            uint32_t vb[4];
            ldm4t(vb, sb + QW + (k * 16 + vrow_off) * 528 + (n16 * 16 + vcol_off) * 2);
            mma16816(o[n16 * 2],     Aa, vb[0], vb[1]);
            mma16816(o[n16 * 2 + 1], Aa, vb[2], vb[3]);
        }
    }

    const int row0 = i0 + w * 16 + g;
    if (mat == 2) {
        #pragma unroll
        for (int nb = 0; nb < 32; nb++) {
            int c = nb * 8 + t4 * 2;
            float b0 = bias[c], b1 = bias[c + 1];
            *(uint32_t*)&g_Vhf[(size_t)row0 * DD + c]       = pack_f16(o[nb][0] + b0, o[nb][1] + b1);
            *(uint32_t*)&g_Vhf[(size_t)(row0 + 8) * DD + c] = pack_f16(o[nb][2] + b0, o[nb][3] + b1);
        }
    } else {
        uint8_t* O8 = (mat == 0) ? g_Qf8 : g_Kf8;
        const float qs = (mat == 0) ? 1.4426950408889634f : 1.0f;  // L2E fold into Q
        #pragma unroll
        for (int nb = 0; nb < 32; nb++) {
            int c = nb * 8 + t4 * 2;
            float b0 = bias[c], b1 = bias[c + 1];
            *(uint16_t*)&O8[(size_t)row0 * DD + c]       = pack_e4m3x2((o[nb][0] + b0) * qs, (o[nb][1] + b1) * qs);
            *(uint16_t*)&O8[(size_t)(row0 + 8) * DD + c] = pack_e4m3x2((o[nb][2] + b0) * qs, (o[nb][3] + b1) * qs);
        }
    }
}

// ---------------------------------------------------------------------------
// K2: flash attention.  fp8 S (log2-domain) + MMA decay exponents + f16 AV.
// 256 thr = 2 ping-pong groups x 4 warps; group g: tiles g, g+2, ...
// Warp rg: S rows rg*16 x 64 keys; decay a via f16 mma (Qp hoisted);
// P register-resident (f16); AV rows x 256 dims (f16 acc).
// softmax-one: H = sum(2^x' V) / (2^M' + sum(2^x')), x' = log2-domain logit.
// ---------------------------------------------------------------------------
#define SQ    0                       // Q fp8 64 x 272 = 17408
#define SQP   17408                   // Qp f16 64 x 32B = 2048
#define SKB   19456                   // K fp8: (g*2+st)*17408, 4 bufs = 69632
#define SKP   89088                   // Kp f16: (g*2+st)*2048, 4 bufs = 8192
#define SVB   97280                   // V f16: g*33792, 2 bufs = 67584
#define SRED  164864                  // m[2][64], l[2][64] = 1024
#define SMEMB 165888
// epilogue: oM f32[64][260] overlays sm[0 .. 66560]

__device__ __forceinline__ void loadK(uint32_t sb, int tg, int g, int tt)
{
    if (tt < 128) {
        const int st = (tt >> 1) & 1;
        const int j0 = tt * 64;
        const uint32_t kb = sb + SKB + (uint32_t)(g * 2 + st) * 17408;
        #pragma unroll
        for (int l = 0; l < 8; l++) {
            int idx = tg + l * 128;
            int r = idx >> 4, c16 = idx & 15;
            cp16(kb + (uint32_t)(r * 272 + c16 * 16),
                 g_Kf8 + (size_t)(j0 + r) * DD + c16 * 16);
        }
        // Kp stage: 64 rows x 32B
        {
            int r = tg >> 1, c = tg & 1;
            cp16(sb + SKP + (uint32_t)(g * 2 + st) * 2048 + (uint32_t)(r * 32 + c * 16),
                 (const char*)g_Pk + ((size_t)(j0 + r) * 16 + c * 8) * 2);
        }
    }
    cp_commit();
}
__device__ __forceinline__ void loadV(uint32_t sb, int tg, int g, int tt)
{
    if (tt < 128) {
        const int j0 = tt * 64;
        const uint32_t vb = sb + SVB + (uint32_t)g * 33792;
        #pragma unroll
        for (int l = 0; l < 16; l++) {
            int idx = tg + l * 128;
            int r = idx >> 5, c8 = idx & 31;
            cp16(vb + (uint32_t)(r * 528 + c8 * 16),
                 (const char*)g_Vhf + ((size_t)(j0 + r) * DD + c8 * 8) * 2);
        }
    }
    cp_commit();
}

__global__ __launch_bounds__(256, 1) void flash_kernel(
    const float* __restrict__ X, float* __restrict__ out)
{
    extern __shared__ char sm[];
    const uint32_t sb = smem_u32(sm);
    const int t = threadIdx.x;
    const int lane = t & 31, w = t >> 5;
    const int rg = w & 3, g = w >> 2;       // group 0/1
    const int tg = t & 127;
    const int lg = lane >> 2, t4 = lane & 3;
    const int i0 = blockIdx.x * 64;
    const int rA = rg * 16 + lg, rB = rA + 8;
    const int barid = 1 + g;

    // stage Q fp8 + Qp (plain stores)
    #pragma unroll
    for (int l = 0; l < 4; l++) {
        int idx = t + l * 256;
        int r = idx >> 4, c16 = idx & 15;
        uint4 v = *(const uint4*)&g_Qf8[(size_t)(i0 + r) * DD + c16 * 16];
        *(uint4*)(sm + SQ + r * 272 + c16 * 16) = v;
    }
    if (t < 128) {
        int r = t >> 1, c = t & 1;
        uint4 v = *(const uint4*)&g_Pq[(size_t)(i0 + r) * 16 + c * 8];
        *(uint4*)(sm + SQP + r * 32 + c * 16) = v;
    }
    // prologue commits: [K(g)], [V(g)], [K(g+2)]
    loadK(sb, tg, g, g);
    loadV(sb, tg, g, g);
    loadK(sb, tg, g, g + 2);
    __syncthreads();   // Q + Qp visible

    // hoist Qp fragment (4 regs, tile-invariant)
    const int qrow = rg * 16 + (lane & 15);
    const int qoff = (lane >> 4) * 16;                        // bytes (8 fp8 / 8 f16*2)
    uint32_t Qpa[4];
    ldm4(Qpa, sb + SQP + qrow * 32 + qoff);

    uint32_t o[32][2];                     // f16x2 accumulators
    #pragma unroll
    for (int i = 0; i < 32; i++) { o[i][0] = 0u; o[i][1] = 0u; }
    float mA = -1e30f, mB = -1e30f;        // running max in log2 domain
    float lA = 0.f, lB = 0.f;

    const int krow_off = ((lane >> 4) << 3) + (lane & 7);
    const int kcol = ((lane >> 3) & 1) * 16;                 // bytes (fp8 K)
    const int kpcol = ((lane >> 3) & 1) * 16;                // bytes (f16 Kp: 8 elems)
    const int vrow_off = ((lane >> 3) & 1) * 8 + (lane & 7);
    const int vcol_off = (lane >> 4) * 8;
    const uint32_t vbase = sb + SVB + (uint32_t)g * 33792;

    #pragma unroll 1
    for (int tt = g; tt < 128; tt += 2) {
        const int st = (tt >> 1) & 1;
        asm volatile("cp.async.wait_group 1;" ::: "memory");  // K(tt), V(tt) done
        bar_sync(barid, 128);

        // ---- S' = L2E * Q K^T (fp8, k32): 16 rows x 64 keys ----
        const uint32_t kbase = sb + SKB + (uint32_t)(g * 2 + st) * 17408;
        float s[8][4];
        #pragma unroll
        for (int i = 0; i < 8; i++)
            #pragma unroll
            for (int j = 0; j < 4; j++) s[i][j] = 0.f;
        #pragma unroll
        for (int k = 0; k < 8; k++) {
            uint32_t Qa[4];
            ldm4(Qa, sb + SQ + qrow * 272 + k * 32 + qoff);
            #pragma unroll
            for (int np = 0; np < 4; np++) {
                uint32_t bf[4];
                ldm4(bf, kbase + (np * 16 + krow_off) * 272 + k * 32 + kcol);
                mma_fp8(s[np * 2],     Qa, bf[0], bf[1]);
                mma_fp8(s[np * 2 + 1], Qa, bf[2], bf[3]);
            }
        }

        // ---- decay exponents a = Qp . Kp (one f16 mma per 16-key block) ----
        const uint32_t kpbase = sb + SKP + (uint32_t)(g * 2 + st) * 2048;
        float a[8][4];
        #pragma unroll
        for (int i = 0; i < 8; i++)
            #pragma unroll
            for (int j = 0; j < 4; j++) a[i][j] = 0.f;
        #pragma unroll
        for (int np = 0; np < 4; np++) {
            uint32_t pf[4];
            ldm4(pf, kpbase + (np * 16 + krow_off) * 32 + kpcol);
            mma16816h(a[np * 2],     Qpa, pf[0], pf[1]);
            mma16816h(a[np * 2 + 1], Qpa, pf[2], pf[3]);
        }

        // ---- x' = s' * 2^min(a,-4); unshifted 2^x' -> register P (f16) ----
        uint32_t aa[4][4];
        #pragma unroll
        for (int nb = 0; nb < 8; nb++) {
            float x0 = s[nb][0] * fexp2(fminf(a[nb][0], -4.0f));
            float x1 = s[nb][1] * fexp2(fminf(a[nb][1], -4.0f));
            float x2 = s[nb][2] * fexp2(fminf(a[nb][2], -4.0f));
            float x3 = s[nb][3] * fexp2(fminf(a[nb][3], -4.0f));
            mA = fmaxf(mA, fmaxf(x0, x1));
            mB = fmaxf(mB, fmaxf(x2, x3));
            float p0 = fexp2(x0), p1 = fexp2(x1);
            float p2 = fexp2(x2), p3 = fexp2(x3);
            lA += p0 + p1; lB += p2 + p3;
            if ((nb & 1) == 0) {
                aa[nb >> 1][0] = pack_f16(p0, p1);
                aa[nb >> 1][1] = pack_f16(p2, p3);
            } else {
                aa[nb >> 1][2] = pack_f16(p0, p1);
                aa[nb >> 1][3] = pack_f16(p2, p3);
            }
        }

        // ---- O += P V (f16 acc): 16 rows x 256 dims, 64 keys ----
        #pragma unroll
        for (int ks = 0; ks < 4; ks++) {
            #pragma unroll
            for (int n16 = 0; n16 < 16; n16++) {
                uint32_t vb[4];
                ldm4t(vb, vbase + (ks * 16 + vrow_off) * 528 + (n16 * 16 + vcol_off) * 2);
                mma_h16(o[n16 * 2],     aa[ks], vb[0], vb[1]);
                mma_h16(o[n16 * 2 + 1], aa[ks], vb[2], vb[3]);
            }
        }
        bar_sync(barid, 128);       // buffers consumed by group
        loadV(sb, tg, g, tt + 2);
        loadK(sb, tg, g, tt + 4);
    }

    // ---- reduce private l/m over quad lanes ----
    lA += __shfl_xor_sync(0xffffffffu, lA, 1);
    lA += __shfl_xor_sync(0xffffffffu, lA, 2);
    lB += __shfl_xor_sync(0xffffffffu, lB, 1);
    lB += __shfl_xor_sync(0xffffffffu, lB, 2);
    mA = fmaxf(mA, __shfl_xor_sync(0xffffffffu, mA, 1));
    mA = fmaxf(mA, __shfl_xor_sync(0xffffffffu, mA, 2));
    mB = fmaxf(mB, __shfl_xor_sync(0xffffffffu, mB, 1));
    mB = fmaxf(mB, __shfl_xor_sync(0xffffffffu, mB, 2));

    float* red = (float*)(sm + SRED);    // m[2][64] then l[2][64]
    if (t4 == 0) {
        red[g * 64 + rA] = mA;       red[g * 64 + rB] = mB;
        red[128 + g * 64 + rA] = lA; red[128 + g * 64 + rB] = lB;
    }
    __syncthreads();     // all compute done; K/V/Q buffers dead

    float* oM = (float*)sm;              // [64][260] f32 overlay
    if (g == 1) {
        #pragma unroll
        for (int nb = 0; nb < 32; nb++) {
            int c = nb * 8 + t4 * 2;
            float2 fA = __half22float2(*reinterpret_cast<const __half2*>(&o[nb][0]));
            float2 fB = __half22float2(*reinterpret_cast<const __half2*>(&o[nb][1]));
            oM[rA * 260 + c] = fA.x; oM[rA * 260 + c + 1] = fA.y;
            oM[rB * 260 + c] = fB.x; oM[rB * 260 + c + 1] = fB.y;
        }
    }
    __syncthreads();
    if (g == 0) {
        float MA = fmaxf(red[rA], red[64 + rA]);
        float MB = fmaxf(red[rB], red[64 + rB]);
        float invA = 1.f / (fexp2(MA) + red[128 + rA] + red[192 + rA]);
        float invB = 1.f / (fexp2(MB) + red[128 + rB] + red[192 + rB]);
        const int gA = i0 + rA, gB = i0 + rB;
        #pragma unroll
        for (int nb = 0; nb < 32; nb++) {
            int c = nb * 8 + t4 * 2;
            float2 fA = __half22float2(*reinterpret_cast<const __half2*>(&o[nb][0]));
            float2 fB = __half22float2(*reinterpret_cast<const __half2*>(&o[nb][1]));
            float2 vA, vB;
            vA.x = (fA.x + oM[rA * 260 + c])     * invA + X[(size_t)gA * XSTR + c];
            vA.y = (fA.y + oM[rA * 260 + c + 1]) * invA + X[(size_t)gA * XSTR + c + 1];
            vB.x = (fB.x + oM[rB * 260 + c])     * invB + X[(size_t)gB * XSTR + c];
            vB.y = (fB.y + oM[rB * 260 + c + 1]) * invB + X[(size_t)gB * XSTR + c + 1];
            *(float2*)&out[(size_t)gA * DD + c] = vA;
            *(float2*)&out[(size_t)gB * DD + c] = vB;
        }
    }
}

// ---------------------------------------------------------------------------
extern "C" void kernel_launch(void* const* d_in, const int* in_sizes, int n_in,
                              void* d_out, int out_size)
{
    const float* X  = (const float*)d_in[0];
    const float* WQ = (const float*)d_in[1];
    const float* bQ = (const float*)d_in[2];
    const float* WK = (const float*)d_in[3];
    const float* bK = (const float*)d_in[4];
    const float* WV = (const float*)d_in[5];
    const float* bV = (const float*)d_in[6];
    float* out = (float*)d_out;

    cudaFuncSetAttribute(flash_kernel, cudaFuncAttributeMaxDynamicSharedMemorySize, SMEMB);
    cudaFuncSetAttribute(qkv_mma_kernel, cudaFuncAttributeMaxDynamicSharedMemorySize, SMEMQ);

    prep_kernel<<<NN * 32 / 256, 256>>>(X);
    wconv_kernel<<<dim3(DD * DD / 8 / 256, 3), 256>>>(WQ, WK, WV);
    qkv_mma_kernel<<<dim3(NN / 128, 3), 256, SMEMQ>>>(bQ, bK, bV);
    flash_kernel<<<NN / 64, 256, SMEMB>>>(X, out);
}

// round 16
// speedup vs baseline: 1.5683x; 1.0164x over previous
#include <cuda_runtime.h>
#include <cuda_bf16.h>
#include <cuda_fp16.h>
#include <cstdint>

#define NN 8192
#define DD 256
#define XSTR 259

// ---------------- device scratch ----------------
__device__ __nv_bfloat16 g_Xbf[NN * DD];
__device__ __nv_bfloat16 g_Wbf[3][DD * DD];
__device__ uint8_t g_Qf8[NN * DD];            // Q e4m3, scaled by L2E (log2-domain scores)
__device__ uint8_t g_Kf8[NN * DD];            // K e4m3
__device__ __half  g_Vhf[NN * DD];            // V f16
__device__ __half  g_Pq[NN * 16];             // decay A-features per row
__device__ __half  g_Pk[NN * 16];             // decay B-features per key

// ---------------- helpers ----------------
__device__ __forceinline__ uint32_t smem_u32(const void* p) {
    uint32_t a;
    asm("{ .reg .u64 t; cvta.to.shared.u64 t, %1; cvt.u32.u64 %0, t; }" : "=r"(a) : "l"(p));
    return a;
}
__device__ __forceinline__ float fexp2(float x) {
    float r;
    asm("ex2.approx.f32 %0, %1;" : "=f"(r) : "f"(x));
    return r;
}
__device__ __forceinline__ uint32_t ex2h2(uint32_t x) {   // 2^x on f16x2 (MUFU, 2 lanes)
    uint32_t r;
    asm("ex2.approx.f16x2 %0, %1;" : "=r"(r) : "r"(x));
    return r;
}
__device__ __forceinline__ uint32_t hmin2(uint32_t a, uint32_t b) {
    uint32_t r;
    asm("min.f16x2 %0, %1, %2;" : "=r"(r) : "r"(a), "r"(b));
    return r;
}
__device__ __forceinline__ uint32_t hmax2(uint32_t a, uint32_t b) {
    uint32_t r;
    asm("max.f16x2 %0, %1, %2;" : "=r"(r) : "r"(a), "r"(b));
    return r;
}
__device__ __forceinline__ uint32_t hadd2(uint32_t a, uint32_t b) {
    uint32_t r;
    asm("add.rn.f16x2 %0, %1, %2;" : "=r"(r) : "r"(a), "r"(b));
    return r;
}
__device__ __forceinline__ uint32_t hmul2(uint32_t a, uint32_t b) {
    uint32_t r;
    asm("mul.rn.f16x2 %0, %1, %2;" : "=r"(r) : "r"(a), "r"(b));
    return r;
}
__device__ __forceinline__ uint32_t pack_bf16(float lo, float hi) {
    uint32_t r;
    asm("cvt.rn.bf16x2.f32 %0, %1, %2;" : "=r"(r) : "f"(hi), "f"(lo));
    return r;
}
__device__ __forceinline__ uint32_t pack_f16(float lo, float hi) {
    uint32_t r;
    asm("cvt.rn.f16x2.f32 %0, %1, %2;" : "=r"(r) : "f"(hi), "f"(lo));
    return r;
}
__device__ __forceinline__ uint16_t pack_e4m3x2(float lo, float hi) {
    uint16_t r;
    asm("cvt.rn.satfinite.e4m3x2.f32 %0, %1, %2;" : "=h"(r) : "f"(hi), "f"(lo));
    return r;
}
__device__ __forceinline__ void cp16(uint32_t s, const void* g) {
    asm volatile("cp.async.cg.shared.global [%0], [%1], 16;" :: "r"(s), "l"(g));
}
__device__ __forceinline__ void cp_commit() {
    asm volatile("cp.async.commit_group;" ::: "memory");
}
__device__ __forceinline__ void ldm4(uint32_t* r, uint32_t a) {
    asm volatile("ldmatrix.sync.aligned.m8n8.x4.shared.b16 {%0,%1,%2,%3}, [%4];"
                 : "=r"(r[0]), "=r"(r[1]), "=r"(r[2]), "=r"(r[3]) : "r"(a));
}
__device__ __forceinline__ void ldm4t(uint32_t* r, uint32_t a) {
    asm volatile("ldmatrix.sync.aligned.m8n8.x4.trans.shared.b16 {%0,%1,%2,%3}, [%4];"
                 : "=r"(r[0]), "=r"(r[1]), "=r"(r[2]), "=r"(r[3]) : "r"(a));
}
__device__ __forceinline__ void mma16816(float* c, const uint32_t* a, uint32_t b0, uint32_t b1) {
    asm volatile(
        "mma.sync.aligned.m16n8k16.row.col.f32.bf16.bf16.f32 "
        "{%0,%1,%2,%3}, {%4,%5,%6,%7}, {%8,%9}, {%0,%1,%2,%3};"
        : "+f"(c[0]), "+f"(c[1]), "+f"(c[2]), "+f"(c[3])
        : "r"(a[0]), "r"(a[1]), "r"(a[2]), "r"(a[3]), "r"(b0), "r"(b1));
}
__device__ __forceinline__ void mma_fp8(float* c, const uint32_t* a, uint32_t b0, uint32_t b1) {
    asm volatile(
        "mma.sync.aligned.m16n8k32.row.col.f32.e4m3.e4m3.f32 "
        "{%0,%1,%2,%3}, {%4,%5,%6,%7}, {%8,%9}, {%0,%1,%2,%3};"
        : "+f"(c[0]), "+f"(c[1]), "+f"(c[2]), "+f"(c[3])
        : "r"(a[0]), "r"(a[1]), "r"(a[2]), "r"(a[3]), "r"(b0), "r"(b1));
}
__device__ __forceinline__ void mma_h16(uint32_t* c, const uint32_t* a, uint32_t b0, uint32_t b1) {
    asm volatile(
        "mma.sync.aligned.m16n8k16.row.col.f16.f16.f16.f16 "
        "{%0,%1}, {%2,%3,%4,%5}, {%6,%7}, {%0,%1};"
        : "+r"(c[0]), "+r"(c[1])
        : "r"(a[0]), "r"(a[1]), "r"(a[2]), "r"(a[3]), "r"(b0), "r"(b1));
}
__device__ __forceinline__ void bar_sync(int id, int cnt) {
    asm volatile("bar.sync %0, %1;" :: "r"(id), "r"(cnt) : "memory");
}

// ---------------------------------------------------------------------------
// K0: prep — X -> bf16, decay feature rows (X rows only 4B-aligned: scalar)
// ---------------------------------------------------------------------------
__global__ __launch_bounds__(256) void prep_kernel(const float* __restrict__ X)
{
    int idx = blockIdx.x * 256 + threadIdx.x;
    int row = idx >> 5, c8 = idx & 31;
    const float* xr = X + (size_t)row * XSTR + c8 * 8;
    float v0 = xr[0], v1 = xr[1], v2 = xr[2], v3 = xr[3];
    float v4 = xr[4], v5 = xr[5], v6 = xr[6], v7 = xr[7];
    uint4 u;
    u.x = pack_bf16(v0, v1); u.y = pack_bf16(v2, v3);
    u.z = pack_bf16(v4, v5); u.w = pack_bf16(v6, v7);
    *(uint4*)&g_Xbf[(size_t)row * DD + c8 * 8] = u;
    if (c8 == 0) {
        const float c2 = 0.72134752f;   // 0.5 * log2(e)
        float px = X[(size_t)row * XSTR + 256];
        float py = X[(size_t)row * XSTR + 257];
        float pz = X[(size_t)row * XSTR + 258];
        float n2 = px*px + py*py + pz*pz;
        uint4 q0;
        q0.x = pack_f16(2.f*c2*px, 2.f*c2*py);
        q0.y = pack_f16(2.f*c2*pz, -(c2*n2 + 4.f));
        q0.z = pack_f16(1.f, 0.f);
        q0.w = 0u;
        *(uint4*)&g_Pq[row * 16]     = q0;
        *(uint4*)&g_Pq[row * 16 + 8] = make_uint4(0u, 0u, 0u, 0u);
        uint4 k0;
        k0.x = pack_f16(px, py);
        k0.y = pack_f16(pz, 1.f);
        k0.z = pack_f16(-c2*n2, 0.f);
        k0.w = 0u;
        *(uint4*)&g_Pk[row * 16]     = k0;
        *(uint4*)&g_Pk[row * 16 + 8] = make_uint4(0u, 0u, 0u, 0u);
    }
}

// ---------------------------------------------------------------------------
// K0b: W -> bf16
// ---------------------------------------------------------------------------
__global__ __launch_bounds__(256) void wconv_kernel(
    const float* __restrict__ WQ, const float* __restrict__ WK, const float* __restrict__ WV)
{
    int mat = blockIdx.y;
    const float* W = (mat == 0) ? WQ : (mat == 1) ? WK : WV;
    int idx = blockIdx.x * 256 + threadIdx.x;
    int base = idx * 8;
    const float4* wr = (const float4*)(W + base);
    float4 a = wr[0], b = wr[1];
    uint4 u;
    u.x = pack_bf16(a.x, a.y); u.y = pack_bf16(a.z, a.w);
    u.z = pack_bf16(b.x, b.y); u.w = pack_bf16(b.z, b.w);
    *(uint4*)&g_Wbf[mat][base] = u;
}

// ---------------------------------------------------------------------------
// K1: QKV via mma.sync.  Q -> e4m3 * L2E, K -> e4m3, V -> f16.
// ---------------------------------------------------------------------------
#define QX 0
#define QW 67584
#define SMEMQ (67584 + 135168)

__global__ __launch_bounds__(256, 1) void qkv_mma_kernel(
    const float* __restrict__ bQ, const float* __restrict__ bK, const float* __restrict__ bV)
{
    extern __shared__ char sm[];
    const uint32_t sb = smem_u32(sm);
    const int t = threadIdx.x, lane = t & 31, w = t >> 5;
    const int g = lane >> 2, t4 = lane & 3;
    const int mat = blockIdx.y;
    const int i0 = blockIdx.x * 128;
    const float* bias = (mat == 0) ? bQ : (mat == 1) ? bK : bV;

    #pragma unroll
    for (int l = 0; l < 16; l++) {
        int idx = t + l * 256;
        int r = idx >> 5, c8 = idx & 31;
        uint4 v = *(const uint4*)&g_Xbf[(size_t)(i0 + r) * DD + c8 * 8];
        *(uint4*)(sm + QX + r * 528 + c8 * 16) = v;
    }
    #pragma unroll
    for (int l = 0; l < 32; l++) {
        int idx = t + l * 256;
        int r = idx >> 5, c8 = idx & 31;
        uint4 v = *(const uint4*)&g_Wbf[mat][(size_t)r * DD + c8 * 8];
        *(uint4*)(sm + QW + r * 528 + c8 * 16) = v;
    }
    __syncthreads();

    float o[32][4];
    #pragma unroll
    for (int i = 0; i < 32; i++)
        #pragma unroll
        for (int j = 0; j < 4; j++) o[i][j] = 0.f;

    const int arow = w * 16 + (lane & 15);
    const int acol = (lane >> 4) * 8;
    const int vrow_off = ((lane >> 3) & 1) * 8 + (lane & 7);
    const int vcol_off = (lane >> 4) * 8;

    #pragma unroll
    for (int k = 0; k < 16; k++) {
        uint32_t Aa[4];
        ldm4(Aa, sb + QX + arow * 528 + (acol + k * 16) * 2);
        #pragma unroll
        for (int n16 = 0; n16 < 16; n16++) {
            uint32_t vb[4];
            ldm4t(vb, sb + QW + (k * 16 + vrow_off) * 528 + (n16 * 16 + vcol_off) * 2);
            mma16816(o[n16 * 2],     Aa, vb[0], vb[1]);
            mma16816(o[n16 * 2 + 1], Aa, vb[2], vb[3]);
        }
    }

    const int row0 = i0 + w * 16 + g;
    if (mat == 2) {
        #pragma unroll
        for (int nb = 0; nb < 32; nb++) {
            int c = nb * 8 + t4 * 2;
            float b0 = bias[c], b1 = bias[c + 1];
            *(uint32_t*)&g_Vhf[(size_t)row0 * DD + c]       = pack_f16(o[nb][0] + b0, o[nb][1] + b1);
            *(uint32_t*)&g_Vhf[(size_t)(row0 + 8) * DD + c] = pack_f16(o[nb][2] + b0, o[nb][3] + b1);
        }
    } else {
        uint8_t* O8 = (mat == 0) ? g_Qf8 : g_Kf8;
        const float qs = (mat == 0) ? 1.4426950408889634f : 1.0f;  // L2E fold into Q
        #pragma unroll
        for (int nb = 0; nb < 32; nb++) {
            int c = nb * 8 + t4 * 2;
            float b0 = bias[c], b1 = bias[c + 1];
            *(uint16_t*)&O8[(size_t)row0 * DD + c]       = pack_e4m3x2((o[nb][0] + b0) * qs, (o[nb][1] + b1) * qs);
            *(uint16_t*)&O8[(size_t)(row0 + 8) * DD + c] = pack_e4m3x2((o[nb][2] + b0) * qs, (o[nb][3] + b1) * qs);
        }
    }
}

// ---------------------------------------------------------------------------
// K2: flash attention.  fp8 S (log2-domain) + f16-acc MMA decay + f16x2
// softmax chain + f16 AV.  2 ping-pong groups x 4 warps.
// ---------------------------------------------------------------------------
#define SQ    0                       // Q fp8 64 x 272 = 17408
#define SQP   17408                   // Qp f16 64 x 32B = 2048
#define SKB   19456                   // K fp8: (g*2+st)*17408, 4 bufs = 69632
#define SKP   89088                   // Kp f16: (g*2+st)*2048, 4 bufs = 8192
#define SVB   97280                   // V f16: g*33792, 2 bufs = 67584
#define SRED  164864                  // m[2][64], l[2][64] = 1024
#define SMEMB 165888
// epilogue: oM f32[64][260] overlays sm[0 .. 66560]

__device__ __forceinline__ void loadK(uint32_t sb, int tg, int g, int tt)
{
    if (tt < 128) {
        const int st = (tt >> 1) & 1;
        const int j0 = tt * 64;
        const uint32_t kb = sb + SKB + (uint32_t)(g * 2 + st) * 17408;
        #pragma unroll
        for (int l = 0; l < 8; l++) {
            int idx = tg + l * 128;
            int r = idx >> 4, c16 = idx & 15;
            cp16(kb + (uint32_t)(r * 272 + c16 * 16),
                 g_Kf8 + (size_t)(j0 + r) * DD + c16 * 16);
        }
        {
            int r = tg >> 1, c = tg & 1;
            cp16(sb + SKP + (uint32_t)(g * 2 + st) * 2048 + (uint32_t)(r * 32 + c * 16),
                 (const char*)g_Pk + ((size_t)(j0 + r) * 16 + c * 8) * 2);
        }
    }
    cp_commit();
}
__device__ __forceinline__ void loadV(uint32_t sb, int tg, int g, int tt)
{
    if (tt < 128) {
        const int j0 = tt * 64;
        const uint32_t vb = sb + SVB + (uint32_t)g * 33792;
        #pragma unroll
        for (int l = 0; l < 16; l++) {
            int idx = tg + l * 128;
            int r = idx >> 5, c8 = idx & 31;
            cp16(vb + (uint32_t)(r * 528 + c8 * 16),
                 (const char*)g_Vhf + ((size_t)(j0 + r) * DD + c8 * 8) * 2);
        }
    }
    cp_commit();
}

__global__ __launch_bounds__(256, 1) void flash_kernel(
    const float* __restrict__ X, float* __restrict__ out)
{
    extern __shared__ char sm[];
    const uint32_t sb = smem_u32(sm);
    const int t = threadIdx.x;
    const int lane = t & 31, w = t >> 5;
    const int rg = w & 3, g = w >> 2;       // group 0/1
    const int tg = t & 127;
    const int lg = lane >> 2, t4 = lane & 3;
    const int i0 = blockIdx.x * 64;
    const int rA = rg * 16 + lg, rB = rA + 8;
    const int barid = 1 + g;

    // stage Q fp8 + Qp
    #pragma unroll
    for (int l = 0; l < 4; l++) {
        int idx = t + l * 256;
        int r = idx >> 4, c16 = idx & 15;
        uint4 v = *(const uint4*)&g_Qf8[(size_t)(i0 + r) * DD + c16 * 16];
        *(uint4*)(sm + SQ + r * 272 + c16 * 16) = v;
    }
    if (t < 128) {
        int r = t >> 1, c = t & 1;
        uint4 v = *(const uint4*)&g_Pq[(size_t)(i0 + r) * 16 + c * 8];
        *(uint4*)(sm + SQP + r * 32 + c * 16) = v;
    }
    loadK(sb, tg, g, g);
    loadV(sb, tg, g, g);
    loadK(sb, tg, g, g + 2);
    __syncthreads();

    // hoist Qp fragment (4 regs, tile-invariant)
    const int qrow = rg * 16 + (lane & 15);
    const int qoff = (lane >> 4) * 16;
    uint32_t Qpa[4];
    ldm4(Qpa, sb + SQP + qrow * 32 + qoff);

    uint32_t o[32][2];                     // f16x2 accumulators
    #pragma unroll
    for (int i = 0; i < 32; i++) { o[i][0] = 0u; o[i][1] = 0u; }
    uint32_t mhA = 0xFC00FC00u, mhB = 0xFC00FC00u;   // -inf f16x2 (max of x')
    float lA = 0.f, lB = 0.f;
    const uint32_t C4H2 = 0xC400C400u;     // (-4, -4) f16x2

    const int krow_off = ((lane >> 4) << 3) + (lane & 7);
    const int kcol = ((lane >> 3) & 1) * 16;
    const int kpcol = ((lane >> 3) & 1) * 16;
    const int vrow_off = ((lane >> 3) & 1) * 8 + (lane & 7);
    const int vcol_off = (lane >> 4) * 8;
    const uint32_t vbase = sb + SVB + (uint32_t)g * 33792;

    #pragma unroll 1
    for (int tt = g; tt < 128; tt += 2) {
        const int st = (tt >> 1) & 1;
        asm volatile("cp.async.wait_group 1;" ::: "memory");
        bar_sync(barid, 128);

        // ---- S' = L2E * Q K^T (fp8, k32): 16 rows x 64 keys ----
        const uint32_t kbase = sb + SKB + (uint32_t)(g * 2 + st) * 17408;
        float s[8][4];
        #pragma unroll
        for (int i = 0; i < 8; i++)
            #pragma unroll
            for (int j = 0; j < 4; j++) s[i][j] = 0.f;
        #pragma unroll
        for (int k = 0; k < 8; k++) {
            uint32_t Qa[4];
            ldm4(Qa, sb + SQ + qrow * 272 + k * 32 + qoff);
            #pragma unroll
            for (int np = 0; np < 4; np++) {
                uint32_t bf[4];
                ldm4(bf, kbase + (np * 16 + krow_off) * 272 + k * 32 + kcol);
                mma_fp8(s[np * 2],     Qa, bf[0], bf[1]);
                mma_fp8(s[np * 2 + 1], Qa, bf[2], bf[3]);
            }
        }

        // ---- decay exponents a = Qp . Kp (f16 acc -> half2 frags) ----
        const uint32_t kpbase = sb + SKP + (uint32_t)(g * 2 + st) * 2048;
        uint32_t ah[8][2];
        #pragma unroll
        for (int i = 0; i < 8; i++) { ah[i][0] = 0u; ah[i][1] = 0u; }
        #pragma unroll
        for (int np = 0; np < 4; np++) {
            uint32_t pf[4];
            ldm4(pf, kpbase + (np * 16 + krow_off) * 32 + kpcol);
            mma_h16(ah[np * 2],     Qpa, pf[0], pf[1]);
            mma_h16(ah[np * 2 + 1], Qpa, pf[2], pf[3]);
        }

        // ---- f16x2 softmax chain: d=2^min(a,-4); x=s*d; p=2^x ----
        uint32_t aa[4][4];
        uint32_t lhA = 0u, lhB = 0u;
        #pragma unroll
        for (int nb = 0; nb < 8; nb++) {
            uint32_t dA = ex2h2(hmin2(ah[nb][0], C4H2));
            uint32_t dB = ex2h2(hmin2(ah[nb][1], C4H2));
            uint32_t shA = pack_f16(s[nb][0], s[nb][1]);
            uint32_t shB = pack_f16(s[nb][2], s[nb][3]);
            uint32_t xA = hmul2(shA, dA);
            uint32_t xB = hmul2(shB, dB);
            mhA = hmax2(mhA, xA);
            mhB = hmax2(mhB, xB);
            uint32_t pA = ex2h2(xA);
            uint32_t pB = ex2h2(xB);
            lhA = hadd2(lhA, pA);
            lhB = hadd2(lhB, pB);
            if ((nb & 1) == 0) {
                aa[nb >> 1][0] = pA;
                aa[nb >> 1][1] = pB;
            } else {
                aa[nb >> 1][2] = pA;
                aa[nb >> 1][3] = pB;
            }
        }
        {   // flush per-iter l sums to f32 (f16 range safe: <=32 * ~23)
            float2 fA = __half22float2(*reinterpret_cast<const __half2*>(&lhA));
            float2 fB = __half22float2(*reinterpret_cast<const __half2*>(&lhB));
            lA += fA.x + fA.y;
            lB += fB.x + fB.y;
        }

        // ---- O += P V (f16 acc): 16 rows x 256 dims, 64 keys ----
        #pragma unroll
        for (int ks = 0; ks < 4; ks++) {
            #pragma unroll
            for (int n16 = 0; n16 < 16; n16++) {
                uint32_t vb[4];
                ldm4t(vb, vbase + (ks * 16 + vrow_off) * 528 + (n16 * 16 + vcol_off) * 2);
                mma_h16(o[n16 * 2],     aa[ks], vb[0], vb[1]);
                mma_h16(o[n16 * 2 + 1], aa[ks], vb[2], vb[3]);
            }
        }
        bar_sync(barid, 128);
        loadV(sb, tg, g, tt + 2);
        loadK(sb, tg, g, tt + 4);
    }

    // ---- finalize m (unpack half2 max), reduce l/m over quad lanes ----
    float mA, mB;
    {
        float2 fA = __half22float2(*reinterpret_cast<const __half2*>(&mhA));
        float2 fB = __half22float2(*reinterpret_cast<const __half2*>(&mhB));
        mA = fmaxf(fA.x, fA.y);
        mB = fmaxf(fB.x, fB.y);
    }
    lA += __shfl_xor_sync(0xffffffffu, lA, 1);
    lA += __shfl_xor_sync(0xffffffffu, lA, 2);
    lB += __shfl_xor_sync(0xffffffffu, lB, 1);
    lB += __shfl_xor_sync(0xffffffffu, lB, 2);
    mA = fmaxf(mA, __shfl_xor_sync(0xffffffffu, mA, 1));
    mA = fmaxf(mA, __shfl_xor_sync(0xffffffffu, mA, 2));
    mB = fmaxf(mB, __shfl_xor_sync(0xffffffffu, mB, 1));
    mB = fmaxf(mB, __shfl_xor_sync(0xffffffffu, mB, 2));

    float* red = (float*)(sm + SRED);    // m[2][64] then l[2][64]
    if (t4 == 0) {
        red[g * 64 + rA] = mA;       red[g * 64 + rB] = mB;
        red[128 + g * 64 + rA] = lA; red[128 + g * 64 + rB] = lB;
    }
    __syncthreads();     // all compute done; K/V/Q buffers dead

    float* oM = (float*)sm;              // [64][260] f32 overlay
    if (g == 1) {
        #pragma unroll
        for (int nb = 0; nb < 32; nb++) {
            int c = nb * 8 + t4 * 2;
            float2 fA = __half22float2(*reinterpret_cast<const __half2*>(&o[nb][0]));
            float2 fB = __half22float2(*reinterpret_cast<const __half2*>(&o[nb][1]));
            oM[rA * 260 + c] = fA.x; oM[rA * 260 + c + 1] = fA.y;
            oM[rB * 260 + c] = fB.x; oM[rB * 260 + c + 1] = fB.y;
        }
    }
    __syncthreads();
    if (g == 0) {
        float MA = fmaxf(red[rA], red[64 + rA]);
        float MB = fmaxf(red[rB], red[64 + rB]);
        float invA = 1.f / (fexp2(MA) + red[128 + rA] + red[192 + rA]);
        float invB = 1.f / (fexp2(MB) + red[128 + rB] + red[192 + rB]);
        const int gA = i0 + rA, gB = i0 + rB;
        #pragma unroll
        for (int nb = 0; nb < 32; nb++) {
            int c = nb * 8 + t4 * 2;
            float2 fA = __half22float2(*reinterpret_cast<const __half2*>(&o[nb][0]));
            float2 fB = __half22float2(*reinterpret_cast<const __half2*>(&o[nb][1]));
            float2 vA, vB;
            vA.x = (fA.x + oM[rA * 260 + c])     * invA + X[(size_t)gA * XSTR + c];
            vA.y = (fA.y + oM[rA * 260 + c + 1]) * invA + X[(size_t)gA * XSTR + c + 1];
            vB.x = (fB.x + oM[rB * 260 + c])     * invB + X[(size_t)gB * XSTR + c];
            vB.y = (fB.y + oM[rB * 260 + c + 1]) * invB + X[(size_t)gB * XSTR + c + 1];
            *(float2*)&out[(size_t)gA * DD + c] = vA;
            *(float2*)&out[(size_t)gB * DD + c] = vB;
        }
    }
}

// ---------------------------------------------------------------------------
extern "C" void kernel_launch(void* const* d_in, const int* in_sizes, int n_in,
                              void* d_out, int out_size)
{
    const float* X  = (const float*)d_in[0];
    const float* WQ = (const float*)d_in[1];
    const float* bQ = (const float*)d_in[2];
    const float* WK = (const float*)d_in[3];
    const float* bK = (const float*)d_in[4];
    const float* WV = (const float*)d_in[5];
    const float* bV = (const float*)d_in[6];
    float* out = (float*)d_out;

    cudaFuncSetAttribute(flash_kernel, cudaFuncAttributeMaxDynamicSharedMemorySize, SMEMB);
    cudaFuncSetAttribute(qkv_mma_kernel, cudaFuncAttributeMaxDynamicSharedMemorySize, SMEMQ);

    prep_kernel<<<NN * 32 / 256, 256>>>(X);
    wconv_kernel<<<dim3(DD * DD / 8 / 256, 3), 256>>>(WQ, WK, WV);
    qkv_mma_kernel<<<dim3(NN / 128, 3), 256, SMEMQ>>>(bQ, bK, bV);
    flash_kernel<<<NN / 64, 256, SMEMB>>>(X, out);
}

// round 17
// speedup vs baseline: 1.6772x; 1.0694x over previous
#include <cuda_runtime.h>
#include <cuda_bf16.h>
#include <cuda_fp16.h>
#include <cstdint>

#define NN 8192
#define DD 256
#define XSTR 259

// ---------------- device scratch ----------------
__device__ __nv_bfloat16 g_Xbf[NN * DD];
__device__ __nv_bfloat16 g_Wbf[3][DD * DD];
__device__ uint8_t g_Qf8[NN * DD];            // Q e4m3, scaled by L2E (log2-domain scores)
__device__ uint8_t g_Kf8[NN * DD];            // K e4m3
__device__ __half  g_Vhf[NN * DD];            // V f16
__device__ __half  g_Pq[NN * 16];             // decay A-features per row
__device__ __half  g_Pk[NN * 16];             // decay B-features per key

// ---------------- helpers ----------------
__device__ __forceinline__ uint32_t smem_u32(const void* p) {
    uint32_t a;
    asm("{ .reg .u64 t; cvta.to.shared.u64 t, %1; cvt.u32.u64 %0, t; }" : "=r"(a) : "l"(p));
    return a;
}
__device__ __forceinline__ float fexp2(float x) {
    float r;
    asm("ex2.approx.f32 %0, %1;" : "=f"(r) : "f"(x));
    return r;
}
__device__ __forceinline__ uint32_t ex2h2(uint32_t x) {   // 2^x on f16x2
    uint32_t r;
    asm("ex2.approx.f16x2 %0, %1;" : "=r"(r) : "r"(x));
    return r;
}
__device__ __forceinline__ uint32_t hmin2(uint32_t a, uint32_t b) {
    uint32_t r;
    asm("min.f16x2 %0, %1, %2;" : "=r"(r) : "r"(a), "r"(b));
    return r;
}
__device__ __forceinline__ uint32_t hmax2(uint32_t a, uint32_t b) {
    uint32_t r;
    asm("max.f16x2 %0, %1, %2;" : "=r"(r) : "r"(a), "r"(b));
    return r;
}
__device__ __forceinline__ uint32_t hadd2(uint32_t a, uint32_t b) {
    uint32_t r;
    asm("add.rn.f16x2 %0, %1, %2;" : "=r"(r) : "r"(a), "r"(b));
    return r;
}
__device__ __forceinline__ uint32_t hmul2(uint32_t a, uint32_t b) {
    uint32_t r;
    asm("mul.rn.f16x2 %0, %1, %2;" : "=r"(r) : "r"(a), "r"(b));
    return r;
}
__device__ __forceinline__ uint32_t pack_bf16(float lo, float hi) {
    uint32_t r;
    asm("cvt.rn.bf16x2.f32 %0, %1, %2;" : "=r"(r) : "f"(hi), "f"(lo));
    return r;
}
__device__ __forceinline__ uint32_t pack_f16(float lo, float hi) {
    uint32_t r;
    asm("cvt.rn.f16x2.f32 %0, %1, %2;" : "=r"(r) : "f"(hi), "f"(lo));
    return r;
}
__device__ __forceinline__ uint16_t pack_e4m3x2(float lo, float hi) {
    uint16_t r;
    asm("cvt.rn.satfinite.e4m3x2.f32 %0, %1, %2;" : "=h"(r) : "f"(hi), "f"(lo));
    return r;
}
__device__ __forceinline__ void cp16(uint32_t s, const void* g) {
    asm volatile("cp.async.cg.shared.global [%0], [%1], 16;" :: "r"(s), "l"(g));
}
__device__ __forceinline__ void cp_commit() {
    asm volatile("cp.async.commit_group;" ::: "memory");
}
__device__ __forceinline__ void ldm4(uint32_t* r, uint32_t a) {
    asm volatile("ldmatrix.sync.aligned.m8n8.x4.shared.b16 {%0,%1,%2,%3}, [%4];"
                 : "=r"(r[0]), "=r"(r[1]), "=r"(r[2]), "=r"(r[3]) : "r"(a));
}
__device__ __forceinline__ void ldm4t(uint32_t* r, uint32_t a) {
    asm volatile("ldmatrix.sync.aligned.m8n8.x4.trans.shared.b16 {%0,%1,%2,%3}, [%4];"
                 : "=r"(r[0]), "=r"(r[1]), "=r"(r[2]), "=r"(r[3]) : "r"(a));
}
__device__ __forceinline__ void mma16816(float* c, const uint32_t* a, uint32_t b0, uint32_t b1) {
    asm volatile(
        "mma.sync.aligned.m16n8k16.row.col.f32.bf16.bf16.f32 "
        "{%0,%1,%2,%3}, {%4,%5,%6,%7}, {%8,%9}, {%0,%1,%2,%3};"
        : "+f"(c[0]), "+f"(c[1]), "+f"(c[2]), "+f"(c[3])
        : "r"(a[0]), "r"(a[1]), "r"(a[2]), "r"(a[3]), "r"(b0), "r"(b1));
}
// fp8 mma with f16 accumulator (2-reg C) — S comes out pre-paired in half2
__device__ __forceinline__ void mma_fp8h(uint32_t* c, const uint32_t* a, uint32_t b0, uint32_t b1) {
    asm volatile(
        "mma.sync.aligned.m16n8k32.row.col.f16.e4m3.e4m3.f16 "
        "{%0,%1}, {%2,%3,%4,%5}, {%6,%7}, {%0,%1};"
        : "+r"(c[0]), "+r"(c[1])
        : "r"(a[0]), "r"(a[1]), "r"(a[2]), "r"(a[3]), "r"(b0), "r"(b1));
}
__device__ __forceinline__ void mma_h16(uint32_t* c, const uint32_t* a, uint32_t b0, uint32_t b1) {
    asm volatile(
        "mma.sync.aligned.m16n8k16.row.col.f16.f16.f16.f16 "
        "{%0,%1}, {%2,%3,%4,%5}, {%6,%7}, {%0,%1};"
        : "+r"(c[0]), "+r"(c[1])
        : "r"(a[0]), "r"(a[1]), "r"(a[2]), "r"(a[3]), "r"(b0), "r"(b1));
}
__device__ __forceinline__ void bar_sync(int id, int cnt) {
    asm volatile("bar.sync %0, %1;" :: "r"(id), "r"(cnt) : "memory");
}

// ---------------------------------------------------------------------------
// K0: prep — X -> bf16, decay feature rows (X rows only 4B-aligned: scalar)
// ---------------------------------------------------------------------------
__global__ __launch_bounds__(256) void prep_kernel(const float* __restrict__ X)
{
    int idx = blockIdx.x * 256 + threadIdx.x;
    int row = idx >> 5, c8 = idx & 31;
    const float* xr = X + (size_t)row * XSTR + c8 * 8;
    float v0 = xr[0], v1 = xr[1], v2 = xr[2], v3 = xr[3];
    float v4 = xr[4], v5 = xr[5], v6 = xr[6], v7 = xr[7];
    uint4 u;
    u.x = pack_bf16(v0, v1); u.y = pack_bf16(v2, v3);
    u.z = pack_bf16(v4, v5); u.w = pack_bf16(v6, v7);
    *(uint4*)&g_Xbf[(size_t)row * DD + c8 * 8] = u;
    if (c8 == 0) {
        const float c2 = 0.72134752f;   // 0.5 * log2(e)
        float px = X[(size_t)row * XSTR + 256];
        float py = X[(size_t)row * XSTR + 257];
        float pz = X[(size_t)row * XSTR + 258];
        float n2 = px*px + py*py + pz*pz;
        uint4 q0;
        q0.x = pack_f16(2.f*c2*px, 2.f*c2*py);
        q0.y = pack_f16(2.f*c2*pz, -(c2*n2 + 4.f));
        q0.z = pack_f16(1.f, 0.f);
        q0.w = 0u;
        *(uint4*)&g_Pq[row * 16]     = q0;
        *(uint4*)&g_Pq[row * 16 + 8] = make_uint4(0u, 0u, 0u, 0u);
        uint4 k0;
        k0.x = pack_f16(px, py);
        k0.y = pack_f16(pz, 1.f);
        k0.z = pack_f16(-c2*n2, 0.f);
        k0.w = 0u;
        *(uint4*)&g_Pk[row * 16]     = k0;
        *(uint4*)&g_Pk[row * 16 + 8] = make_uint4(0u, 0u, 0u, 0u);
    }
}

// ---------------------------------------------------------------------------
// K0b: W -> bf16
// ---------------------------------------------------------------------------
__global__ __launch_bounds__(256) void wconv_kernel(
    const float* __restrict__ WQ, const float* __restrict__ WK, const float* __restrict__ WV)
{
    int mat = blockIdx.y;
    const float* W = (mat == 0) ? WQ : (mat == 1) ? WK : WV;
    int idx = blockIdx.x * 256 + threadIdx.x;
    int base = idx * 8;
    const float4* wr = (const float4*)(W + base);
    float4 a = wr[0], b = wr[1];
    uint4 u;
    u.x = pack_bf16(a.x, a.y); u.y = pack_bf16(a.z, a.w);
    u.z = pack_bf16(b.x, b.y); u.w = pack_bf16(b.z, b.w);
    *(uint4*)&g_Wbf[mat][base] = u;
}

// ---------------------------------------------------------------------------
// K1: QKV via mma.sync.  Q -> e4m3 * L2E, K -> e4m3, V -> f16.
// ---------------------------------------------------------------------------
#define QX 0
#define QW 67584
#define SMEMQ (67584 + 135168)

__global__ __launch_bounds__(256, 1) void qkv_mma_kernel(
    const float* __restrict__ bQ, const float* __restrict__ bK, const float* __restrict__ bV)
{
    extern __shared__ char sm[];
    const uint32_t sb = smem_u32(sm);
    const int t = threadIdx.x, lane = t & 31, w = t >> 5;
    const int g = lane >> 2, t4 = lane & 3;
    const int mat = blockIdx.y;
    const int i0 = blockIdx.x * 128;
    const float* bias = (mat == 0) ? bQ : (mat == 1) ? bK : bV;

    #pragma unroll
    for (int l = 0; l < 16; l++) {
        int idx = t + l * 256;
        int r = idx >> 5, c8 = idx & 31;
        uint4 v = *(const uint4*)&g_Xbf[(size_t)(i0 + r) * DD + c8 * 8];
        *(uint4*)(sm + QX + r * 528 + c8 * 16) = v;
    }
    #pragma unroll
    for (int l = 0; l < 32; l++) {
        int idx = t + l * 256;
        int r = idx >> 5, c8 = idx & 31;
        uint4 v = *(const uint4*)&g_Wbf[mat][(size_t)r * DD + c8 * 8];
        *(uint4*)(sm + QW + r * 528 + c8 * 16) = v;
    }
    __syncthreads();

    float o[32][4];
    #pragma unroll
    for (int i = 0; i < 32; i++)
        #pragma unroll
        for (int j = 0; j < 4; j++) o[i][j] = 0.f;

    const int arow = w * 16 + (lane & 15);
    const int acol = (lane >> 4) * 8;
    const int vrow_off = ((lane >> 3) & 1) * 8 + (lane & 7);
    const int vcol_off = (lane >> 4) * 8;

    #pragma unroll
    for (int k = 0; k < 16; k++) {
        uint32_t Aa[4];
        ldm4(Aa, sb + QX + arow * 528 + (acol + k * 16) * 2);
        #pragma unroll
        for (int n16 = 0; n16 < 16; n16++) {
            uint32_t vb[4];
            ldm4t(vb, sb + QW + (k * 16 + vrow_off) * 528 + (n16 * 16 + vcol_off) * 2);
            mma16816(o[n16 * 2],     Aa, vb[0], vb[1]);
            mma16816(o[n16 * 2 + 1], Aa, vb[2], vb[3]);
        }
    }

    const int row0 = i0 + w * 16 + g;
    if (mat == 2) {
        #pragma unroll
        for (int nb = 0; nb < 32; nb++) {
            int c = nb * 8 + t4 * 2;
            float b0 = bias[c], b1 = bias[c + 1];
            *(uint32_t*)&g_Vhf[(size_t)row0 * DD + c]       = pack_f16(o[nb][0] + b0, o[nb][1] + b1);
            *(uint32_t*)&g_Vhf[(size_t)(row0 + 8) * DD + c] = pack_f16(o[nb][2] + b0, o[nb][3] + b1);
        }
    } else {
        uint8_t* O8 = (mat == 0) ? g_Qf8 : g_Kf8;
        const float qs = (mat == 0) ? 1.4426950408889634f : 1.0f;  // L2E fold into Q
        #pragma unroll
        for (int nb = 0; nb < 32; nb++) {
            int c = nb * 8 + t4 * 2;
            float b0 = bias[c], b1 = bias[c + 1];
            *(uint16_t*)&O8[(size_t)row0 * DD + c]       = pack_e4m3x2((o[nb][0] + b0) * qs, (o[nb][1] + b1) * qs);
            *(uint16_t*)&O8[(size_t)(row0 + 8) * DD + c] = pack_e4m3x2((o[nb][2] + b0) * qs, (o[nb][3] + b1) * qs);
        }
    }
}

// ---------------------------------------------------------------------------
// K2: flash attention.  fp8 S w/ f16 acc (log2-domain) + f16-acc MMA decay +
// f16x2 softmax chain + f16 AV.  2 ping-pong groups x 4 warps.  Qa hoisted.
// ---------------------------------------------------------------------------
#define SQ    0                       // Q fp8 64 x 272 = 17408
#define SQP   17408                   // Qp f16 64 x 32B = 2048
#define SKB   19456                   // K fp8: (g*2+st)*17408, 4 bufs = 69632
#define SKP   89088                   // Kp f16: (g*2+st)*2048, 4 bufs = 8192
#define SVB   97280                   // V f16: g*33792, 2 bufs = 67584
#define SRED  164864                  // m[2][64], l[2][64] = 1024
#define SMEMB 165888
// epilogue: oM f32[64][260] overlays sm[0 .. 66560]

__device__ __forceinline__ void loadK(uint32_t sb, int tg, int g, int tt)
{
    if (tt < 128) {
        const int st = (tt >> 1) & 1;
        const int j0 = tt * 64;
        const uint32_t kb = sb + SKB + (uint32_t)(g * 2 + st) * 17408;
        #pragma unroll
        for (int l = 0; l < 8; l++) {
            int idx = tg + l * 128;
            int r = idx >> 4, c16 = idx & 15;
            cp16(kb + (uint32_t)(r * 272 + c16 * 16),
                 g_Kf8 + (size_t)(j0 + r) * DD + c16 * 16);
        }
        {
            int r = tg >> 1, c = tg & 1;
            cp16(sb + SKP + (uint32_t)(g * 2 + st) * 2048 + (uint32_t)(r * 32 + c * 16),
                 (const char*)g_Pk + ((size_t)(j0 + r) * 16 + c * 8) * 2);
        }
    }
    cp_commit();
}
__device__ __forceinline__ void loadV(uint32_t sb, int tg, int g, int tt)
{
    if (tt < 128) {
        const int j0 = tt * 64;
        const uint32_t vb = sb + SVB + (uint32_t)g * 33792;
        #pragma unroll
        for (int l = 0; l < 16; l++) {
            int idx = tg + l * 128;
            int r = idx >> 5, c8 = idx & 31;
            cp16(vb + (uint32_t)(r * 528 + c8 * 16),
                 (const char*)g_Vhf + ((size_t)(j0 + r) * DD + c8 * 8) * 2);
        }
    }
    cp_commit();
}

__global__ __launch_bounds__(256, 1) void flash_kernel(
    const float* __restrict__ X, float* __restrict__ out)
{
    extern __shared__ char sm[];
    const uint32_t sb = smem_u32(sm);
    const int t = threadIdx.x;
    const int lane = t & 31, w = t >> 5;
    const int rg = w & 3, g = w >> 2;       // group 0/1
    const int tg = t & 127;
    const int lg = lane >> 2, t4 = lane & 3;
    const int i0 = blockIdx.x * 64;
    const int rA = rg * 16 + lg, rB = rA + 8;
    const int barid = 1 + g;

    // stage Q fp8 + Qp
    #pragma unroll
    for (int l = 0; l < 4; l++) {
        int idx = t + l * 256;
        int r = idx >> 4, c16 = idx & 15;
        uint4 v = *(const uint4*)&g_Qf8[(size_t)(i0 + r) * DD + c16 * 16];
        *(uint4*)(sm + SQ + r * 272 + c16 * 16) = v;
    }
    if (t < 128) {
        int r = t >> 1, c = t & 1;
        uint4 v = *(const uint4*)&g_Pq[(size_t)(i0 + r) * 16 + c * 8];
        *(uint4*)(sm + SQP + r * 32 + c * 16) = v;
    }
    loadK(sb, tg, g, g);
    loadV(sb, tg, g, g);
    loadK(sb, tg, g, g + 2);
    __syncthreads();

    // hoist Qp + Qa fragments (tile-invariant)
    const int qrow = rg * 16 + (lane & 15);
    const int qoff = (lane >> 4) * 16;
    uint32_t Qpa[4];
    ldm4(Qpa, sb + SQP + qrow * 32 + qoff);
    uint32_t Qa[8][4];
    #pragma unroll
    for (int k = 0; k < 8; k++)
        ldm4(Qa[k], sb + SQ + qrow * 272 + k * 32 + qoff);

    uint32_t o[32][2];                     // f16x2 accumulators
    #pragma unroll
    for (int i = 0; i < 32; i++) { o[i][0] = 0u; o[i][1] = 0u; }
    uint32_t mhA = 0xFC00FC00u, mhB = 0xFC00FC00u;   // -inf f16x2 (max of x')
    float lA = 0.f, lB = 0.f;
    const uint32_t C4H2 = 0xC400C400u;     // (-4, -4) f16x2

    const int krow_off = ((lane >> 4) << 3) + (lane & 7);
    const int kcol = ((lane >> 3) & 1) * 16;
    const int kpcol = ((lane >> 3) & 1) * 16;
    const int vrow_off = ((lane >> 3) & 1) * 8 + (lane & 7);
    const int vcol_off = (lane >> 4) * 8;
    const uint32_t vbase = sb + SVB + (uint32_t)g * 33792;

    #pragma unroll 1
    for (int tt = g; tt < 128; tt += 2) {
        const int st = (tt >> 1) & 1;
        asm volatile("cp.async.wait_group 1;" ::: "memory");
        bar_sync(barid, 128);

        // ---- S' = L2E * Q K^T (fp8, f16 acc): 16 rows x 64 keys ----
        const uint32_t kbase = sb + SKB + (uint32_t)(g * 2 + st) * 17408;
        uint32_t sh[8][2];
        #pragma unroll
        for (int i = 0; i < 8; i++) { sh[i][0] = 0u; sh[i][1] = 0u; }
        #pragma unroll
        for (int k = 0; k < 8; k++) {
            #pragma unroll
            for (int np = 0; np < 4; np++) {
                uint32_t bf[4];
                ldm4(bf, kbase + (np * 16 + krow_off) * 272 + k * 32 + kcol);
                mma_fp8h(sh[np * 2],     Qa[k], bf[0], bf[1]);
                mma_fp8h(sh[np * 2 + 1], Qa[k], bf[2], bf[3]);
            }
        }

        // ---- decay exponents a = Qp . Kp (f16 acc) ----
        const uint32_t kpbase = sb + SKP + (uint32_t)(g * 2 + st) * 2048;
        uint32_t ah[8][2];
        #pragma unroll
        for (int i = 0; i < 8; i++) { ah[i][0] = 0u; ah[i][1] = 0u; }
        #pragma unroll
        for (int np = 0; np < 4; np++) {
            uint32_t pf[4];
            ldm4(pf, kpbase + (np * 16 + krow_off) * 32 + kpcol);
            mma_h16(ah[np * 2],     Qpa, pf[0], pf[1]);
            mma_h16(ah[np * 2 + 1], Qpa, pf[2], pf[3]);
        }

        // ---- f16x2 softmax chain: d=2^min(a,-4); x=s*d; p=2^x ----
        uint32_t aa[4][4];
        uint32_t lhA = 0u, lhB = 0u;
        #pragma unroll
        for (int nb = 0; nb < 8; nb++) {
            uint32_t dA = ex2h2(hmin2(ah[nb][0], C4H2));
            uint32_t dB = ex2h2(hmin2(ah[nb][1], C4H2));
            uint32_t xA = hmul2(sh[nb][0], dA);
            uint32_t xB = hmul2(sh[nb][1], dB);
            mhA = hmax2(mhA, xA);
            mhB = hmax2(mhB, xB);
            uint32_t pA = ex2h2(xA);
            uint32_t pB = ex2h2(xB);
            lhA = hadd2(lhA, pA);
            lhB = hadd2(lhB, pB);
            if ((nb & 1) == 0) {
                aa[nb >> 1][0] = pA;
                aa[nb >> 1][1] = pB;
            } else {
                aa[nb >> 1][2] = pA;
                aa[nb >> 1][3] = pB;
            }
        }
        {
            float2 fA = __half22float2(*reinterpret_cast<const __half2*>(&lhA));
            float2 fB = __half22float2(*reinterpret_cast<const __half2*>(&lhB));
            lA += fA.x + fA.y;
            lB += fB.x + fB.y;
        }

        // ---- O += P V (f16 acc): 16 rows x 256 dims, 64 keys ----
        #pragma unroll
        for (int ks = 0; ks < 4; ks++) {
            #pragma unroll
            for (int n16 = 0; n16 < 16; n16++) {
                uint32_t vb[4];
                ldm4t(vb, vbase + (ks * 16 + vrow_off) * 528 + (n16 * 16 + vcol_off) * 2);
                mma_h16(o[n16 * 2],     aa[ks], vb[0], vb[1]);
                mma_h16(o[n16 * 2 + 1], aa[ks], vb[2], vb[3]);
            }
        }
        bar_sync(barid, 128);
        loadV(sb, tg, g, tt + 2);
        loadK(sb, tg, g, tt + 4);
    }

    // ---- finalize m, reduce l/m over quad lanes ----
    float mA, mB;
    {
        float2 fA = __half22float2(*reinterpret_cast<const __half2*>(&mhA));
        float2 fB = __half22float2(*reinterpret_cast<const __half2*>(&mhB));
        mA = fmaxf(fA.x, fA.y);
        mB = fmaxf(fB.x, fB.y);
    }
    lA += __shfl_xor_sync(0xffffffffu, lA, 1);
    lA += __shfl_xor_sync(0xffffffffu, lA, 2);
    lB += __shfl_xor_sync(0xffffffffu, lB, 1);
    lB += __shfl_xor_sync(0xffffffffu, lB, 2);
    mA = fmaxf(mA, __shfl_xor_sync(0xffffffffu, mA, 1));
    mA = fmaxf(mA, __shfl_xor_sync(0xffffffffu, mA, 2));
    mB = fmaxf(mB, __shfl_xor_sync(0xffffffffu, mB, 1));
    mB = fmaxf(mB, __shfl_xor_sync(0xffffffffu, mB, 2));

    float* red = (float*)(sm + SRED);    // m[2][64] then l[2][64]
    if (t4 == 0) {
        red[g * 64 + rA] = mA;       red[g * 64 + rB] = mB;
        red[128 + g * 64 + rA] = lA; red[128 + g * 64 + rB] = lB;
    }
    __syncthreads();     // all compute done; K/V/Q buffers dead

    float* oM = (float*)sm;              // [64][260] f32 overlay
    if (g == 1) {
        #pragma unroll
        for (int nb = 0; nb < 32; nb++) {
            int c = nb * 8 + t4 * 2;
            float2 fA = __half22float2(*reinterpret_cast<const __half2*>(&o[nb][0]));
            float2 fB = __half22float2(*reinterpret_cast<const __half2*>(&o[nb][1]));
            oM[rA * 260 + c] = fA.x; oM[rA * 260 + c + 1] = fA.y;
            oM[rB * 260 + c] = fB.x; oM[rB * 260 + c + 1] = fB.y;
        }
    }
    __syncthreads();
    if (g == 0) {
        float MA = fmaxf(red[rA], red[64 + rA]);
        float MB = fmaxf(red[rB], red[64 + rB]);
        float invA = 1.f / (fexp2(MA) + red[128 + rA] + red[192 + rA]);
        float invB = 1.f / (fexp2(MB) + red[128 + rB] + red[192 + rB]);
        const int gA = i0 + rA, gB = i0 + rB;
        #pragma unroll
        for (int nb = 0; nb < 32; nb++) {
            int c = nb * 8 + t4 * 2;
            float2 fA = __half22float2(*reinterpret_cast<const __half2*>(&o[nb][0]));
            float2 fB = __half22float2(*reinterpret_cast<const __half2*>(&o[nb][1]));
            float2 vA, vB;
            vA.x = (fA.x + oM[rA * 260 + c])     * invA + X[(size_t)gA * XSTR + c];
            vA.y = (fA.y + oM[rA * 260 + c + 1]) * invA + X[(size_t)gA * XSTR + c + 1];
            vB.x = (fB.x + oM[rB * 260 + c])     * invB + X[(size_t)gB * XSTR + c];
            vB.y = (fB.y + oM[rB * 260 + c + 1]) * invB + X[(size_t)gB * XSTR + c + 1];
            *(float2*)&out[(size_t)gA * DD + c] = vA;
            *(float2*)&out[(size_t)gB * DD + c] = vB;
        }
    }
}

// ---------------------------------------------------------------------------
extern "C" void kernel_launch(void* const* d_in, const int* in_sizes, int n_in,
                              void* d_out, int out_size)
{
    const float* X  = (const float*)d_in[0];
    const float* WQ = (const float*)d_in[1];
    const float* bQ = (const float*)d_in[2];
    const float* WK = (const float*)d_in[3];
    const float* bK = (const float*)d_in[4];
    const float* WV = (const float*)d_in[5];
    const float* bV = (const float*)d_in[6];
    float* out = (float*)d_out;

    cudaFuncSetAttribute(flash_kernel, cudaFuncAttributeMaxDynamicSharedMemorySize, SMEMB);
    cudaFuncSetAttribute(qkv_mma_kernel, cudaFuncAttributeMaxDynamicSharedMemorySize, SMEMQ);

    prep_kernel<<<NN * 32 / 256, 256>>>(X);
    wconv_kernel<<<dim3(DD * DD / 8 / 256, 3), 256>>>(WQ, WK, WV);
    qkv_mma_kernel<<<dim3(NN / 128, 3), 256, SMEMQ>>>(bQ, bK, bV);
    flash_kernel<<<NN / 64, 256, SMEMB>>>(X, out);
}